// round 1
// baseline (speedup 1.0000x reference)
#include <cuda_runtime.h>
#include <math.h>

// Problem constants
#define BSZ   32
#define LEN   28          // IN_LEN == OUT_LEN
#define NNODE 2048
#define EDIM  256
#define HDIM  512
#define MROWS (BSZ*NNODE) // 65536

// Scratch (device globals — no allocation allowed in kernel_launch)
__device__ float g_hbuf[(size_t)MROWS * HDIM];   // 128 MB
__device__ float g_zbuf[(size_t)MROWS * HDIM];   // 128 MB
__device__ float g_bvec[MROWS];
__device__ float g_gvec[MROWS];

// ---------------------------------------------------------------------------
// Stage A: ts = flat @ W_ts^T + b_ts ; h = concat(ts, node_emb)
// flat[b,n,l] = x_node[b,l,n,0]
// One block = 64 consecutive rows (same batch b), 256 threads = one thread per
// output column e in [0,256).
// ---------------------------------------------------------------------------
__global__ __launch_bounds__(256) void ts_kernel(
    const float* __restrict__ x_node,
    const float* __restrict__ node_emb,
    const float* __restrict__ W_ts,
    const float* __restrict__ b_ts)
{
    __shared__ float sW[EDIM * LEN];   // 256*28 floats = 28 KB
    __shared__ float sF[64 * LEN];     // 64 rows * 28

    const int rowBase = blockIdx.x * 64;
    const int bidx  = rowBase >> 11;     // / 2048
    const int nBase = rowBase & 2047;
    const int tid = threadIdx.x;

    for (int i = tid; i < EDIM * LEN; i += 256) sW[i] = W_ts[i];
    for (int idx = tid; idx < 64 * LEN; idx += 256) {
        int l = idx >> 6;      // / 64
        int i = idx & 63;
        sF[i * LEN + l] = x_node[((size_t)(bidx * LEN + l)) * NNODE + nBase + i];
    }
    __syncthreads();

    const int e = tid;                    // 0..255
    const float bias = b_ts[e];
    const float* wrow = &sW[e * LEN];

    for (int i = 0; i < 64; i++) {
        float acc = bias;
        #pragma unroll
        for (int l = 0; l < LEN; l++)
            acc = fmaf(sF[i * LEN + l], wrow[l], acc);
        size_t r = (size_t)(rowBase + i) * HDIM;
        g_hbuf[r + e]        = acc;
        g_hbuf[r + EDIM + e] = node_emb[(size_t)(nBase + i) * EDIM + e];
    }
}

// ---------------------------------------------------------------------------
// Stage B: SGEMM  C[row][col] = sum_k A[row][k]*W[col][k] (+bias, +add, relu)
// M=65536, N=512, K=512. Block tile 128x128, K-step 8, 8x8 microtile,
// 256 threads, register prefetch of next global tile.
// ---------------------------------------------------------------------------
template <bool RELU, bool ADDIN>
__global__ __launch_bounds__(256) void gemm_k(
    const float* __restrict__ A,       // M x 512
    const float* __restrict__ W,       // 512 x 512 (N-major rows, K contiguous)
    const float* __restrict__ bias,    // 512
    const float* __restrict__ addsrc,  // M x 512 (residual) or unused
    float* __restrict__ C)             // M x 512
{
    __shared__ float As[8][132];       // [k][row], padded
    __shared__ float Bs[8][132];       // [k][col], padded

    const int tid = threadIdx.x;
    const int tx = tid & 15;           // 0..15 -> 8 cols each
    const int ty = tid >> 4;           // 0..15 -> 8 rows each
    const int rowBase = blockIdx.y * 128;
    const int colBase = blockIdx.x * 128;

    const int lrow = tid >> 1;         // 0..127
    const int lk4  = (tid & 1) * 4;    // 0 or 4

    const float* Aptr = A + (size_t)(rowBase + lrow) * HDIM + lk4;
    const float* Wptr = W + (size_t)(colBase + lrow) * HDIM + lk4;

    float c[8][8];
    #pragma unroll
    for (int i = 0; i < 8; i++)
        #pragma unroll
        for (int j = 0; j < 8; j++) c[i][j] = 0.f;

    float4 av = *reinterpret_cast<const float4*>(Aptr);
    float4 wv = *reinterpret_cast<const float4*>(Wptr);

    for (int kk = 0; kk < HDIM; kk += 8) {
        As[lk4 + 0][lrow] = av.x; As[lk4 + 1][lrow] = av.y;
        As[lk4 + 2][lrow] = av.z; As[lk4 + 3][lrow] = av.w;
        Bs[lk4 + 0][lrow] = wv.x; Bs[lk4 + 1][lrow] = wv.y;
        Bs[lk4 + 2][lrow] = wv.z; Bs[lk4 + 3][lrow] = wv.w;
        __syncthreads();

        // prefetch next K-slab (dummy reload of slab 0 on the last iter)
        const int kn = (kk + 8 < HDIM) ? (kk + 8) : 0;
        av = *reinterpret_cast<const float4*>(Aptr + kn);
        wv = *reinterpret_cast<const float4*>(Wptr + kn);

        #pragma unroll
        for (int p = 0; p < 8; p++) {
            const float4 a0 = *reinterpret_cast<const float4*>(&As[p][ty * 8]);
            const float4 a1 = *reinterpret_cast<const float4*>(&As[p][ty * 8 + 4]);
            const float4 b0 = *reinterpret_cast<const float4*>(&Bs[p][tx * 8]);
            const float4 b1 = *reinterpret_cast<const float4*>(&Bs[p][tx * 8 + 4]);
            const float a[8] = {a0.x, a0.y, a0.z, a0.w, a1.x, a1.y, a1.z, a1.w};
            const float b[8] = {b0.x, b0.y, b0.z, b0.w, b1.x, b1.y, b1.z, b1.w};
            #pragma unroll
            for (int i = 0; i < 8; i++)
                #pragma unroll
                for (int j = 0; j < 8; j++)
                    c[i][j] = fmaf(a[i], b[j], c[i][j]);
        }
        __syncthreads();
    }

    // Epilogue
    float bcol[8];
    #pragma unroll
    for (int j = 0; j < 8; j++) bcol[j] = bias[colBase + tx * 8 + j];

    #pragma unroll
    for (int i = 0; i < 8; i++) {
        const size_t row = (size_t)(rowBase + ty * 8 + i);
        float* crow = C + row * HDIM + colBase + tx * 8;
        float v[8];
        #pragma unroll
        for (int j = 0; j < 8; j++) v[j] = c[i][j] + bcol[j];
        if (ADDIN) {
            const float* arow = addsrc + row * HDIM + colBase + tx * 8;
            const float4 r0 = *reinterpret_cast<const float4*>(arow);
            const float4 r1 = *reinterpret_cast<const float4*>(arow + 4);
            v[0] += r0.x; v[1] += r0.y; v[2] += r0.z; v[3] += r0.w;
            v[4] += r1.x; v[5] += r1.y; v[6] += r1.z; v[7] += r1.w;
        }
        if (RELU) {
            #pragma unroll
            for (int j = 0; j < 8; j++) v[j] = fmaxf(v[j], 0.f);
        }
        float4 o0 = make_float4(v[0], v[1], v[2], v[3]);
        float4 o1 = make_float4(v[4], v[5], v[6], v[7]);
        *reinterpret_cast<float4*>(crow)     = o0;
        *reinterpret_cast<float4*>(crow + 4) = o1;
    }
}

// ---------------------------------------------------------------------------
// Stage C: b = sigmoid(h @ Wb^T + bb), g = sigmoid(h @ Wg^T + bg)
// One warp per row; 8 rows per block.
// ---------------------------------------------------------------------------
__global__ __launch_bounds__(256) void bg_kernel(
    const float* __restrict__ Wb, const float* __restrict__ bbias,
    const float* __restrict__ Wg, const float* __restrict__ gbias)
{
    __shared__ float sWb[HDIM];
    __shared__ float sWg[HDIM];
    const int tid = threadIdx.x;
    for (int i = tid; i < HDIM; i += 256) { sWb[i] = Wb[i]; sWg[i] = Wg[i]; }
    __syncthreads();

    const int warp = tid >> 5;
    const int lane = tid & 31;
    const size_t row = (size_t)blockIdx.x * 8 + warp;
    const float* hr = g_hbuf + row * HDIM;

    float accb = 0.f, accg = 0.f;
    #pragma unroll
    for (int i = 0; i < HDIM / 32; i++) {
        const int idx = lane + i * 32;
        const float hv = hr[idx];
        accb = fmaf(hv, sWb[idx], accb);
        accg = fmaf(hv, sWg[idx], accg);
    }
    #pragma unroll
    for (int o = 16; o; o >>= 1) {
        accb += __shfl_xor_sync(0xFFFFFFFFu, accb, o);
        accg += __shfl_xor_sync(0xFFFFFFFFu, accg, o);
    }
    if (lane == 0) {
        g_bvec[row] = 1.f / (1.f + expf(-(accb + bbias[0])));
        g_gvec[row] = 1.f / (1.f + expf(-(accg + gbias[0])));
    }
}

// ---------------------------------------------------------------------------
// Stage D: SIR history reconstruction + 28-step scan. One thread per (b, n).
// x_state layout: [B, LEN, NNODE, 3]
// ---------------------------------------------------------------------------
__global__ __launch_bounds__(256) void sim_kernel(
    const float* __restrict__ x_state, float* __restrict__ out)
{
    const size_t r = (size_t)blockIdx.x * blockDim.x + threadIdx.x;
    const int b = (int)(r >> 11);      // / 2048
    const int n = (int)(r & 2047);

    const float beta = g_bvec[r];
    const float g    = g_gvec[r];
    const float decay = expf(-g);
    const float inv_g = 1.f / g;

    const float* xs = x_state + ((size_t)b * LEN * NNODE + n) * 3;
    const int TSTRIDE = NNODE * 3;      // 6144

    // Iin history fold: acc_t = acc_{t-1}*decay + Iin[t-1]
    float Iprev = xs[0 * TSTRIDE + 1];
    float acc = 0.f;
    #pragma unroll
    for (int t = 1; t <= LEN - 1; t++) {
        const float Icur = xs[t * TSTRIDE + 1];
        // Iin_hist[t-1] = (I_hist[t] - I_hist[t-1]) + x_state[t-1,1]
        const float iin = fmaxf((Icur - Iprev) * inv_g + Iprev, 0.f);
        acc = fmaf(acc, decay, iin);
        Iprev = Icur;
    }

    const float Npop  = xs[(LEN - 1) * TSTRIDE + 2];
    const float R_Tm1 = Npop - xs[(LEN - 2) * TSTRIDE + 0];
    const float I_Tm1 = decay * acc;
    const float S_Tm1 = Npop - I_Tm1 - R_Tm1;
    const float Iin0  = beta * S_Tm1 * I_Tm1 / Npop;

    float S = S_Tm1 - Iin0;
    float I = decay * (I_Tm1 + Iin0);   // = sum_t exp(-g*(LEN-t)) * Iin_hist[t]

    float* op = out + (size_t)b * LEN * NNODE + n;
    #pragma unroll
    for (int t = 0; t < LEN; t++) {
        const float Iin = beta * S * I / Npop;
        S -= Iin;
        const float Rin = g * I;
        I = decay * (I + Iin);
        op[(size_t)t * NNODE] = Rin;
    }
}

// ---------------------------------------------------------------------------
extern "C" void kernel_launch(void* const* d_in, const int* in_sizes, int n_in,
                              void* d_out, int out_size)
{
    (void)in_sizes; (void)n_in; (void)out_size;
    const float* x_node   = (const float*)d_in[0];
    const float* x_state  = (const float*)d_in[1];
    const float* node_emb = (const float*)d_in[2];
    const float* W_ts     = (const float*)d_in[3];
    const float* b_ts     = (const float*)d_in[4];
    const float* enc_W1   = (const float*)d_in[5];
    const float* enc_b1   = (const float*)d_in[6];
    const float* enc_W2   = (const float*)d_in[7];
    const float* enc_b2   = (const float*)d_in[8];
    const float* Wb       = (const float*)d_in[9];
    const float* bb       = (const float*)d_in[10];
    const float* Wg       = (const float*)d_in[11];
    const float* bg       = (const float*)d_in[12];
    float* out = (float*)d_out;

    float *hbuf = nullptr, *zbuf = nullptr;
    cudaGetSymbolAddress((void**)&hbuf, g_hbuf);
    cudaGetSymbolAddress((void**)&zbuf, g_zbuf);

    // Stage A: build h = [ts | node_emb]
    ts_kernel<<<MROWS / 64, 256>>>(x_node, node_emb, W_ts, b_ts);

    // Stage B: 3 residual MLP layers
    const dim3 grid(HDIM / 128, MROWS / 128);   // (4, 512)
    for (int l = 0; l < 3; l++) {
        const float* W1 = enc_W1 + (size_t)l * HDIM * HDIM;
        const float* B1 = enc_b1 + (size_t)l * HDIM;
        const float* W2 = enc_W2 + (size_t)l * HDIM * HDIM;
        const float* B2 = enc_b2 + (size_t)l * HDIM;
        gemm_k<true,  false><<<grid, 256>>>(hbuf, W1, B1, nullptr, zbuf);
        gemm_k<false, true ><<<grid, 256>>>(zbuf, W2, B2, hbuf, hbuf);
    }

    // Stage C: b, g
    bg_kernel<<<MROWS / 8, 256>>>(Wb, bb, Wg, bg);

    // Stage D: SIR simulation -> output
    sim_kernel<<<MROWS / 256, 256>>>(x_state, out);
}

// round 3
// speedup vs baseline: 1.7647x; 1.7647x over previous
#include <cuda_runtime.h>
#include <cuda_bf16.h>
#include <math.h>
#include <stdint.h>

// Problem constants
#define BSZ   32
#define LEN   28
#define NNODE 2048
#define EDIM  256
#define HDIM  512
#define MROWS (BSZ*NNODE) // 65536

// GEMM tiling (mma.sync path)
#define BM 128
#define BN 128
#define BK 32
#define NCHUNK (HDIM/BK)    // 16
#define PITCH 80            // bytes per smem row (64B data + 16B pad)
#define OAH 0
#define OAL (128*PITCH)     // 10240
#define OWH (2*128*PITCH)   // 20480
#define OWL (3*128*PITCH)   // 30720
#define STAGE (4*128*PITCH) // 40960
#define NSTAGE 3
#define DSMEM (NSTAGE*STAGE) // 122880

// ---------------------------------------------------------------------------
// Device scratch
// ---------------------------------------------------------------------------
__device__ float g_hbuf[(size_t)MROWS * HDIM];          // fp32 h (residual / bg)
__device__ __nv_bfloat16 g_ahi[(size_t)MROWS * HDIM];
__device__ __nv_bfloat16 g_alo[(size_t)MROWS * HDIM];
__device__ __nv_bfloat16 g_zhi[(size_t)MROWS * HDIM];
__device__ __nv_bfloat16 g_zlo[(size_t)MROWS * HDIM];
__device__ __nv_bfloat16 g_w1hi[3 * HDIM * HDIM];
__device__ __nv_bfloat16 g_w1lo[3 * HDIM * HDIM];
__device__ __nv_bfloat16 g_w2hi[3 * HDIM * HDIM];
__device__ __nv_bfloat16 g_w2lo[3 * HDIM * HDIM];
__device__ float g_bvec[MROWS];
__device__ float g_gvec[MROWS];

// ---------------------------------------------------------------------------
// PTX helpers (baseline sm_80+ features only — no tcgen05 on this target)
// ---------------------------------------------------------------------------
__device__ __forceinline__ uint32_t smem_u32(const void* p) {
    uint32_t a;
    asm("{ .reg .u64 t; cvta.to.shared.u64 t, %1; cvt.u32.u64 %0, t; }" : "=r"(a) : "l"(p));
    return a;
}
__device__ __forceinline__ void cp16(uint32_t dst, const void* src) {
    asm volatile("cp.async.cg.shared.global [%0], [%1], 16;" :: "r"(dst), "l"(src));
}
#define CP_COMMIT() asm volatile("cp.async.commit_group;" ::: "memory")
#define CP_WAIT(n)  asm volatile("cp.async.wait_group %0;" :: "n"(n) : "memory")

__device__ __forceinline__ void ldsm_x4(uint32_t r[4], uint32_t addr) {
    asm volatile("ldmatrix.sync.aligned.m8n8.x4.shared.b16 {%0,%1,%2,%3}, [%4];"
        : "=r"(r[0]), "=r"(r[1]), "=r"(r[2]), "=r"(r[3]) : "r"(addr));
}
__device__ __forceinline__ void ldsm_x2(uint32_t r[2], uint32_t addr) {
    asm volatile("ldmatrix.sync.aligned.m8n8.x2.shared.b16 {%0,%1}, [%2];"
        : "=r"(r[0]), "=r"(r[1]) : "r"(addr));
}
__device__ __forceinline__ void mma_bf16(float c[4], const uint32_t a[4], const uint32_t b[2]) {
    asm volatile("mma.sync.aligned.m16n8k16.row.col.f32.bf16.bf16.f32 "
        "{%0,%1,%2,%3}, {%4,%5,%6,%7}, {%8,%9}, {%0,%1,%2,%3};"
        : "+f"(c[0]), "+f"(c[1]), "+f"(c[2]), "+f"(c[3])
        : "r"(a[0]), "r"(a[1]), "r"(a[2]), "r"(a[3]), "r"(b[0]), "r"(b[1]));
}

__device__ __forceinline__ void bsplit(float x, __nv_bfloat16& h, __nv_bfloat16& l) {
    h = __float2bfloat16_rn(x);
    l = __float2bfloat16_rn(x - __bfloat162float(h));
}

// ---------------------------------------------------------------------------
// Weight conversion: fp32 -> bf16 hi/lo
// ---------------------------------------------------------------------------
__global__ __launch_bounds__(256) void wconv_kernel(const float* __restrict__ W1,
                                                    const float* __restrict__ W2)
{
    const int i = blockIdx.x * 256 + threadIdx.x;
    if (i >= 3 * HDIM * HDIM) return;
    __nv_bfloat16 h, l;
    bsplit(W1[i], h, l); g_w1hi[i] = h; g_w1lo[i] = l;
    bsplit(W2[i], h, l); g_w2hi[i] = h; g_w2lo[i] = l;
}

// ---------------------------------------------------------------------------
// Stage A: ts GEMM (K=28) + concat node_emb ; writes fp32 h and bf16 hi/lo
// ---------------------------------------------------------------------------
__global__ __launch_bounds__(256) void ts_kernel(
    const float* __restrict__ x_node,
    const float* __restrict__ node_emb,
    const float* __restrict__ W_ts,
    const float* __restrict__ b_ts)
{
    __shared__ float sW[EDIM * LEN];
    __shared__ float sF[64 * LEN];

    const int rowBase = blockIdx.x * 64;
    const int bidx  = rowBase >> 11;
    const int nBase = rowBase & 2047;
    const int tid = threadIdx.x;

    for (int i = tid; i < EDIM * LEN; i += 256) sW[i] = W_ts[i];
    for (int idx = tid; idx < 64 * LEN; idx += 256) {
        int l = idx >> 6;
        int i = idx & 63;
        sF[i * LEN + l] = x_node[((size_t)(bidx * LEN + l)) * NNODE + nBase + i];
    }
    __syncthreads();

    const int e = tid;
    const float bias = b_ts[e];
    const float* wrow = &sW[e * LEN];

    for (int i = 0; i < 64; i++) {
        float acc = bias;
        #pragma unroll
        for (int l = 0; l < LEN; l++)
            acc = fmaf(sF[i * LEN + l], wrow[l], acc);
        const size_t r = (size_t)(rowBase + i) * HDIM;
        const float ne = node_emb[(size_t)(nBase + i) * EDIM + e];
        g_hbuf[r + e]        = acc;
        g_hbuf[r + EDIM + e] = ne;
        __nv_bfloat16 h, l;
        bsplit(acc, h, l); g_ahi[r + e] = h;        g_alo[r + e] = l;
        bsplit(ne, h, l);  g_ahi[r + EDIM + e] = h; g_alo[r + EDIM + e] = l;
    }
}

// ---------------------------------------------------------------------------
// bf16x3 split GEMM on mma.sync: C = A @ W^T (+bias)(+residual)(relu)
// M=65536, N=512, K=512. CTA tile 128x128, BK=32, 3-stage cp.async.
// 8 warps: warp_m = wid&1 (2), warp_n = wid>>1 (4); warp tile 64x32.
// ---------------------------------------------------------------------------
template <bool RELU, bool ADDIN, bool WF32, bool WBF16>
__global__ void __launch_bounds__(256, 1) gemm_mma(
    const __nv_bfloat16* __restrict__ Ahi, const __nv_bfloat16* __restrict__ Alo,
    const __nv_bfloat16* __restrict__ Whi, const __nv_bfloat16* __restrict__ Wlo,
    const float* __restrict__ bias,
    const float* __restrict__ addsrc,
    float* __restrict__ outf,
    __nv_bfloat16* __restrict__ outhi, __nv_bfloat16* __restrict__ outlo)
{
    extern __shared__ char dsm[];
    __shared__ float sbias[BN];

    const int tid = threadIdx.x;
    const int wid = tid >> 5;
    const int lane = tid & 31;
    const int warp_m = wid & 1;
    const int warp_n = wid >> 1;
    const int rowBase = blockIdx.y * BM;
    const int colBase = blockIdx.x * BN;

    if (tid < BN) sbias[tid] = bias[colBase + tid];

    const uint32_t sb = smem_u32(dsm);

    float c[4][4][4];
    #pragma unroll
    for (int i = 0; i < 4; i++)
        #pragma unroll
        for (int j = 0; j < 4; j++)
            #pragma unroll
            for (int k = 0; k < 4; k++) c[i][j][k] = 0.f;

    // ---- chunk loader: 512 16B-chunks per array, 2 per thread ----
    auto load_chunk = [&](int cidx, int s) {
        const uint32_t base = sb + (uint32_t)s * STAGE;
        const int kk = cidx * BK;
        #pragma unroll
        for (int j = 0; j < 2; j++) {
            const int ch = tid * 2 + j;
            const int row = ch >> 2;
            const int q = ch & 3;
            const uint32_t doff = (uint32_t)(row * PITCH + q * 16);
            const int eoff = kk + q * 8;       // element offset (8 bf16 per 16B)
            cp16(base + OAH + doff, Ahi + (size_t)(rowBase + row) * HDIM + eoff);
            cp16(base + OAL + doff, Alo + (size_t)(rowBase + row) * HDIM + eoff);
            cp16(base + OWH + doff, Whi + (size_t)(colBase + row) * HDIM + eoff);
            cp16(base + OWL + doff, Wlo + (size_t)(colBase + row) * HDIM + eoff);
        }
        CP_COMMIT();
    };

    // ---- per-stage compute: 2 k16 steps ----
    auto compute = [&](int s) {
        const uint32_t base = sb + (uint32_t)s * STAGE;
        const uint32_t aHb = base + OAH + (uint32_t)((warp_m * 64 + (lane & 15)) * PITCH + (lane >> 4) * 16);
        const uint32_t aLb = aHb + (OAL - OAH);
        const uint32_t wHb = base + OWH + (uint32_t)((warp_n * 32 + (lane & 7)) * PITCH + ((lane >> 3) & 1) * 16);
        const uint32_t wLb = wHb + (OWL - OWH);
        #pragma unroll
        for (int ks = 0; ks < 2; ks++) {
            uint32_t ah[4][4], al[4][4];
            #pragma unroll
            for (int mf = 0; mf < 4; mf++) {
                ldsm_x4(ah[mf], aHb + (uint32_t)(mf * 16 * PITCH + ks * 32));
                ldsm_x4(al[mf], aLb + (uint32_t)(mf * 16 * PITCH + ks * 32));
            }
            #pragma unroll
            for (int nf = 0; nf < 4; nf++) {
                uint32_t bh[2], bl[2];
                ldsm_x2(bh, wHb + (uint32_t)(nf * 8 * PITCH + ks * 32));
                ldsm_x2(bl, wLb + (uint32_t)(nf * 8 * PITCH + ks * 32));
                #pragma unroll
                for (int mf = 0; mf < 4; mf++) {
                    mma_bf16(c[mf][nf], ah[mf], bh);
                    mma_bf16(c[mf][nf], ah[mf], bl);
                    mma_bf16(c[mf][nf], al[mf], bh);
                }
            }
        }
    };

    load_chunk(0, 0);
    load_chunk(1, 1);

    for (int m = 0; m < NCHUNK; m++) {
        if (m == NCHUNK - 1) { CP_WAIT(0); } else { CP_WAIT(1); }
        __syncthreads();
        if (m + 2 < NCHUNK) load_chunk(m + 2, (m + 2) % NSTAGE);
        compute(m % NSTAGE);
    }

    // ---- epilogue: fragments -> smem staging (coalesce), then gmem ----
    __syncthreads();
    float* stg = (float*)dsm;   // 128 x 132 fp32 = 67584 B (fits in stage mem)
    #pragma unroll
    for (int mf = 0; mf < 4; mf++) {
        #pragma unroll
        for (int nf = 0; nf < 4; nf++) {
            const int r0 = warp_m * 64 + mf * 16 + (lane >> 2);
            const int cc = warp_n * 32 + nf * 8 + 2 * (lane & 3);
            *(float2*)&stg[(size_t)r0 * 132 + cc]       = make_float2(c[mf][nf][0], c[mf][nf][1]);
            *(float2*)&stg[(size_t)(r0 + 8) * 132 + cc] = make_float2(c[mf][nf][2], c[mf][nf][3]);
        }
    }
    __syncthreads();

    for (int rr = 0; rr < 16; rr++) {
        const int r = wid * 16 + rr;
        const size_t grow = (size_t)(rowBase + r) * HDIM;
        #pragma unroll
        for (int p = 0; p < 4; p++) {
            const int col = p * 32 + lane;
            float v = stg[(size_t)r * 132 + col] + sbias[col];
            const size_t gi = grow + colBase + col;
            if (ADDIN) v += addsrc[gi];
            if (RELU)  v = fmaxf(v, 0.f);
            if (WF32)  outf[gi] = v;
            if (WBF16) {
                __nv_bfloat16 h, l;
                bsplit(v, h, l);
                outhi[gi] = h; outlo[gi] = l;
            }
        }
    }
}

// ---------------------------------------------------------------------------
// Stage C: b = sigmoid(h@Wb^T+bb), g = sigmoid(h@Wg^T+bg)
// ---------------------------------------------------------------------------
__global__ __launch_bounds__(256) void bg_kernel(
    const float* __restrict__ Wb, const float* __restrict__ bbias,
    const float* __restrict__ Wg, const float* __restrict__ gbias)
{
    __shared__ float sWb[HDIM];
    __shared__ float sWg[HDIM];
    const int tid = threadIdx.x;
    for (int i = tid; i < HDIM; i += 256) { sWb[i] = Wb[i]; sWg[i] = Wg[i]; }
    __syncthreads();

    const int warp = tid >> 5;
    const int lane = tid & 31;
    const size_t row = (size_t)blockIdx.x * 8 + warp;
    const float* hr = g_hbuf + row * HDIM;

    float accb = 0.f, accg = 0.f;
    #pragma unroll
    for (int i = 0; i < HDIM / 32; i++) {
        const int idx = lane + i * 32;
        const float hv = hr[idx];
        accb = fmaf(hv, sWb[idx], accb);
        accg = fmaf(hv, sWg[idx], accg);
    }
    #pragma unroll
    for (int o = 16; o; o >>= 1) {
        accb += __shfl_xor_sync(0xFFFFFFFFu, accb, o);
        accg += __shfl_xor_sync(0xFFFFFFFFu, accg, o);
    }
    if (lane == 0) {
        g_bvec[row] = 1.f / (1.f + expf(-(accb + bbias[0])));
        g_gvec[row] = 1.f / (1.f + expf(-(accg + gbias[0])));
    }
}

// ---------------------------------------------------------------------------
// Stage D: SIR reconstruction + 28-step scan
// ---------------------------------------------------------------------------
__global__ __launch_bounds__(256) void sim_kernel(
    const float* __restrict__ x_state, float* __restrict__ out)
{
    const size_t r = (size_t)blockIdx.x * blockDim.x + threadIdx.x;
    const int b = (int)(r >> 11);
    const int n = (int)(r & 2047);

    const float beta = g_bvec[r];
    const float g    = g_gvec[r];
    const float decay = expf(-g);
    const float inv_g = 1.f / g;

    const float* xs = x_state + ((size_t)b * LEN * NNODE + n) * 3;
    const int TSTRIDE = NNODE * 3;

    float Iprev = xs[0 * TSTRIDE + 1];
    float acc = 0.f;
    #pragma unroll
    for (int t = 1; t <= LEN - 1; t++) {
        const float Icur = xs[t * TSTRIDE + 1];
        const float iin = fmaxf((Icur - Iprev) * inv_g + Iprev, 0.f);
        acc = fmaf(acc, decay, iin);
        Iprev = Icur;
    }

    const float Npop  = xs[(LEN - 1) * TSTRIDE + 2];
    const float R_Tm1 = Npop - xs[(LEN - 2) * TSTRIDE + 0];
    const float I_Tm1 = decay * acc;
    const float S_Tm1 = Npop - I_Tm1 - R_Tm1;
    const float Iin0  = beta * S_Tm1 * I_Tm1 / Npop;

    float S = S_Tm1 - Iin0;
    float I = decay * (I_Tm1 + Iin0);

    float* op = out + (size_t)b * LEN * NNODE + n;
    #pragma unroll
    for (int t = 0; t < LEN; t++) {
        const float Iin = beta * S * I / Npop;
        S -= Iin;
        const float Rin = g * I;
        I = decay * (I + Iin);
        op[(size_t)t * NNODE] = Rin;
    }
}

// ---------------------------------------------------------------------------
extern "C" void kernel_launch(void* const* d_in, const int* in_sizes, int n_in,
                              void* d_out, int out_size)
{
    (void)in_sizes; (void)n_in; (void)out_size;
    const float* x_node   = (const float*)d_in[0];
    const float* x_state  = (const float*)d_in[1];
    const float* node_emb = (const float*)d_in[2];
    const float* W_ts     = (const float*)d_in[3];
    const float* b_ts     = (const float*)d_in[4];
    const float* enc_W1   = (const float*)d_in[5];
    const float* enc_b1   = (const float*)d_in[6];
    const float* enc_W2   = (const float*)d_in[7];
    const float* enc_b2   = (const float*)d_in[8];
    const float* Wb       = (const float*)d_in[9];
    const float* bb       = (const float*)d_in[10];
    const float* Wg       = (const float*)d_in[11];
    const float* bg       = (const float*)d_in[12];
    float* out = (float*)d_out;

    float *hbuf = nullptr;
    __nv_bfloat16 *ahi, *alo, *zhi, *zlo, *w1hi, *w1lo, *w2hi, *w2lo;
    cudaGetSymbolAddress((void**)&hbuf, g_hbuf);
    cudaGetSymbolAddress((void**)&ahi, g_ahi);
    cudaGetSymbolAddress((void**)&alo, g_alo);
    cudaGetSymbolAddress((void**)&zhi, g_zhi);
    cudaGetSymbolAddress((void**)&zlo, g_zlo);
    cudaGetSymbolAddress((void**)&w1hi, g_w1hi);
    cudaGetSymbolAddress((void**)&w1lo, g_w1lo);
    cudaGetSymbolAddress((void**)&w2hi, g_w2hi);
    cudaGetSymbolAddress((void**)&w2lo, g_w2lo);

    cudaFuncSetAttribute(gemm_mma<true,  false, false, true >, cudaFuncAttributeMaxDynamicSharedMemorySize, DSMEM);
    cudaFuncSetAttribute(gemm_mma<false, true,  true,  true >, cudaFuncAttributeMaxDynamicSharedMemorySize, DSMEM);
    cudaFuncSetAttribute(gemm_mma<false, true,  true,  false>, cudaFuncAttributeMaxDynamicSharedMemorySize, DSMEM);

    // weights -> bf16 hi/lo
    wconv_kernel<<<(3 * HDIM * HDIM + 255) / 256, 256>>>(enc_W1, enc_W2);

    // Stage A
    ts_kernel<<<MROWS / 64, 256>>>(x_node, node_emb, W_ts, b_ts);

    // Stage B: 3 residual layers on tensor cores (mma.sync)
    const dim3 grid(HDIM / BN, MROWS / BM);   // (4, 512)
    for (int l = 0; l < 3; l++) {
        const __nv_bfloat16* W1h = w1hi + (size_t)l * HDIM * HDIM;
        const __nv_bfloat16* W1l = w1lo + (size_t)l * HDIM * HDIM;
        const __nv_bfloat16* W2h = w2hi + (size_t)l * HDIM * HDIM;
        const __nv_bfloat16* W2l = w2lo + (size_t)l * HDIM * HDIM;
        const float* B1 = enc_b1 + (size_t)l * HDIM;
        const float* B2 = enc_b2 + (size_t)l * HDIM;

        gemm_mma<true, false, false, true><<<grid, 256, DSMEM>>>(
            ahi, alo, W1h, W1l, B1, nullptr, nullptr, zhi, zlo);

        if (l < 2) {
            gemm_mma<false, true, true, true><<<grid, 256, DSMEM>>>(
                zhi, zlo, W2h, W2l, B2, hbuf, hbuf, ahi, alo);
        } else {
            gemm_mma<false, true, true, false><<<grid, 256, DSMEM>>>(
                zhi, zlo, W2h, W2l, B2, hbuf, hbuf, nullptr, nullptr);
        }
    }

    // Stage C + D
    bg_kernel<<<MROWS / 8, 256>>>(Wb, bb, Wg, bg);
    sim_kernel<<<MROWS / 256, 256>>>(x_state, out);
}

// round 4
// speedup vs baseline: 2.1004x; 1.1902x over previous
#include <cuda_runtime.h>
#include <cuda_bf16.h>
#include <math.h>
#include <stdint.h>

// Problem constants
#define BSZ   32
#define LEN   28
#define NNODE 2048
#define EDIM  256
#define HDIM  512
#define MROWS (BSZ*NNODE) // 65536

// GEMM tiling (mma.sync path)
#define BM 128
#define BN 128
#define BK 32
#define NCHUNK (HDIM/BK)    // 16
#define PITCH 80            // bytes per smem row (64B data + 16B pad) -> conflict-free ldmatrix
#define OAH 0
#define OAL (128*PITCH)     // 10240
#define OWH (2*128*PITCH)   // 20480
#define OWL (3*128*PITCH)   // 30720
#define STAGE (4*128*PITCH) // 40960
#define NSTAGE 2
#define DSMEM (NSTAGE*STAGE) // 81920 -> 2 CTAs/SM

// ---------------------------------------------------------------------------
// Device scratch
// ---------------------------------------------------------------------------
__device__ float g_hbuf[(size_t)MROWS * HDIM];          // fp32 h (residual / bg)
__device__ __nv_bfloat16 g_ahi[(size_t)MROWS * HDIM];
__device__ __nv_bfloat16 g_alo[(size_t)MROWS * HDIM];
__device__ __nv_bfloat16 g_zhi[(size_t)MROWS * HDIM];
__device__ __nv_bfloat16 g_zlo[(size_t)MROWS * HDIM];
__device__ __nv_bfloat16 g_w1hi[3 * HDIM * HDIM];
__device__ __nv_bfloat16 g_w1lo[3 * HDIM * HDIM];
__device__ __nv_bfloat16 g_w2hi[3 * HDIM * HDIM];
__device__ __nv_bfloat16 g_w2lo[3 * HDIM * HDIM];
__device__ float g_bvec[MROWS];
__device__ float g_gvec[MROWS];

// ---------------------------------------------------------------------------
// PTX helpers (baseline sm_80+ features only — no tcgen05 on this target)
// ---------------------------------------------------------------------------
__device__ __forceinline__ uint32_t smem_u32(const void* p) {
    uint32_t a;
    asm("{ .reg .u64 t; cvta.to.shared.u64 t, %1; cvt.u32.u64 %0, t; }" : "=r"(a) : "l"(p));
    return a;
}
__device__ __forceinline__ void cp16(uint32_t dst, const void* src) {
    asm volatile("cp.async.cg.shared.global [%0], [%1], 16;" :: "r"(dst), "l"(src));
}
#define CP_COMMIT() asm volatile("cp.async.commit_group;" ::: "memory")
#define CP_WAIT(n)  asm volatile("cp.async.wait_group %0;" :: "n"(n) : "memory")

__device__ __forceinline__ void ldsm_x4(uint32_t r[4], uint32_t addr) {
    asm volatile("ldmatrix.sync.aligned.m8n8.x4.shared.b16 {%0,%1,%2,%3}, [%4];"
        : "=r"(r[0]), "=r"(r[1]), "=r"(r[2]), "=r"(r[3]) : "r"(addr));
}
__device__ __forceinline__ void ldsm_x2(uint32_t r[2], uint32_t addr) {
    asm volatile("ldmatrix.sync.aligned.m8n8.x2.shared.b16 {%0,%1}, [%2];"
        : "=r"(r[0]), "=r"(r[1]) : "r"(addr));
}
__device__ __forceinline__ void mma_bf16(float c[4], const uint32_t a[4], const uint32_t b[2]) {
    asm volatile("mma.sync.aligned.m16n8k16.row.col.f32.bf16.bf16.f32 "
        "{%0,%1,%2,%3}, {%4,%5,%6,%7}, {%8,%9}, {%0,%1,%2,%3};"
        : "+f"(c[0]), "+f"(c[1]), "+f"(c[2]), "+f"(c[3])
        : "r"(a[0]), "r"(a[1]), "r"(a[2]), "r"(a[3]), "r"(b[0]), "r"(b[1]));
}

__device__ __forceinline__ void bsplit(float x, __nv_bfloat16& h, __nv_bfloat16& l) {
    h = __float2bfloat16_rn(x);
    l = __float2bfloat16_rn(x - __bfloat162float(h));
}

// ---------------------------------------------------------------------------
// Weight conversion: fp32 -> bf16 hi/lo
// ---------------------------------------------------------------------------
__global__ __launch_bounds__(256) void wconv_kernel(const float* __restrict__ W1,
                                                    const float* __restrict__ W2)
{
    const int i = blockIdx.x * 256 + threadIdx.x;
    if (i >= 3 * HDIM * HDIM) return;
    __nv_bfloat16 h, l;
    bsplit(W1[i], h, l); g_w1hi[i] = h; g_w1lo[i] = l;
    bsplit(W2[i], h, l); g_w2hi[i] = h; g_w2lo[i] = l;
}

// ---------------------------------------------------------------------------
// Stage A: ts GEMM (K=28) + concat node_emb ; writes fp32 h and bf16 hi/lo
// ---------------------------------------------------------------------------
__global__ __launch_bounds__(256) void ts_kernel(
    const float* __restrict__ x_node,
    const float* __restrict__ node_emb,
    const float* __restrict__ W_ts,
    const float* __restrict__ b_ts)
{
    __shared__ float sW[EDIM * LEN];
    __shared__ float sF[64 * LEN];

    const int rowBase = blockIdx.x * 64;
    const int bidx  = rowBase >> 11;
    const int nBase = rowBase & 2047;
    const int tid = threadIdx.x;

    for (int i = tid; i < EDIM * LEN; i += 256) sW[i] = W_ts[i];
    for (int idx = tid; idx < 64 * LEN; idx += 256) {
        int l = idx >> 6;
        int i = idx & 63;
        sF[i * LEN + l] = x_node[((size_t)(bidx * LEN + l)) * NNODE + nBase + i];
    }
    __syncthreads();

    const int e = tid;
    const float bias = b_ts[e];
    const float* wrow = &sW[e * LEN];

    for (int i = 0; i < 64; i++) {
        float acc = bias;
        #pragma unroll
        for (int l = 0; l < LEN; l++)
            acc = fmaf(sF[i * LEN + l], wrow[l], acc);
        const size_t r = (size_t)(rowBase + i) * HDIM;
        const float ne = node_emb[(size_t)(nBase + i) * EDIM + e];
        g_hbuf[r + e]        = acc;
        g_hbuf[r + EDIM + e] = ne;
        __nv_bfloat16 h, l;
        bsplit(acc, h, l); g_ahi[r + e] = h;        g_alo[r + e] = l;
        bsplit(ne, h, l);  g_ahi[r + EDIM + e] = h; g_alo[r + EDIM + e] = l;
    }
}

// ---------------------------------------------------------------------------
// bf16x3 split GEMM on mma.sync: C = A @ W^T (+bias)(+residual)(relu)
// M=65536, N=512, K=512. CTA tile 128x128, BK=32, 2-stage cp.async,
// 2 CTAs/SM for phase-staggered overlap.
// ---------------------------------------------------------------------------
template <bool RELU, bool ADDIN, bool WF32, bool WBF16>
__global__ void __launch_bounds__(256, 2) gemm_mma(
    const __nv_bfloat16* __restrict__ Ahi, const __nv_bfloat16* __restrict__ Alo,
    const __nv_bfloat16* __restrict__ Whi, const __nv_bfloat16* __restrict__ Wlo,
    const float* __restrict__ bias,
    const float* __restrict__ addsrc,
    float* __restrict__ outf,
    __nv_bfloat16* __restrict__ outhi, __nv_bfloat16* __restrict__ outlo)
{
    extern __shared__ char dsm[];
    __shared__ float sbias[BN];

    const int tid = threadIdx.x;
    const int wid = tid >> 5;
    const int lane = tid & 31;
    const int warp_m = wid & 1;
    const int warp_n = wid >> 1;
    const int rowBase = blockIdx.y * BM;
    const int colBase = blockIdx.x * BN;

    if (tid < BN) sbias[tid] = bias[colBase + tid];

    const uint32_t sb = smem_u32(dsm);

    float c[4][4][4];
    #pragma unroll
    for (int i = 0; i < 4; i++)
        #pragma unroll
        for (int j = 0; j < 4; j++)
            #pragma unroll
            for (int k = 0; k < 4; k++) c[i][j][k] = 0.f;

    // ---- chunk loader: 512 16B-chunks per array, 2 per thread ----
    auto load_chunk = [&](int cidx, int s) {
        const uint32_t base = sb + (uint32_t)s * STAGE;
        const int kk = cidx * BK;
        #pragma unroll
        for (int j = 0; j < 2; j++) {
            const int ch = tid * 2 + j;
            const int row = ch >> 2;
            const int q = ch & 3;
            const uint32_t doff = (uint32_t)(row * PITCH + q * 16);
            const int eoff = kk + q * 8;       // element offset (8 bf16 per 16B)
            cp16(base + OAH + doff, Ahi + (size_t)(rowBase + row) * HDIM + eoff);
            cp16(base + OAL + doff, Alo + (size_t)(rowBase + row) * HDIM + eoff);
            cp16(base + OWH + doff, Whi + (size_t)(colBase + row) * HDIM + eoff);
            cp16(base + OWL + doff, Wlo + (size_t)(colBase + row) * HDIM + eoff);
        }
        CP_COMMIT();
    };

    // ---- per-stage compute: 2 k16 steps ----
    auto compute = [&](int s) {
        const uint32_t base = sb + (uint32_t)s * STAGE;
        const uint32_t aHb = base + OAH + (uint32_t)((warp_m * 64 + (lane & 15)) * PITCH + (lane >> 4) * 16);
        const uint32_t aLb = aHb + (OAL - OAH);
        const uint32_t wHb = base + OWH + (uint32_t)((warp_n * 32 + (lane & 7)) * PITCH + ((lane >> 3) & 1) * 16);
        const uint32_t wLb = wHb + (OWL - OWH);
        #pragma unroll
        for (int ks = 0; ks < 2; ks++) {
            uint32_t ah[4][4], al[4][4];
            #pragma unroll
            for (int mf = 0; mf < 4; mf++) {
                ldsm_x4(ah[mf], aHb + (uint32_t)(mf * 16 * PITCH + ks * 32));
                ldsm_x4(al[mf], aLb + (uint32_t)(mf * 16 * PITCH + ks * 32));
            }
            #pragma unroll
            for (int nf = 0; nf < 4; nf++) {
                uint32_t bh[2], bl[2];
                ldsm_x2(bh, wHb + (uint32_t)(nf * 8 * PITCH + ks * 32));
                ldsm_x2(bl, wLb + (uint32_t)(nf * 8 * PITCH + ks * 32));
                #pragma unroll
                for (int mf = 0; mf < 4; mf++) {
                    mma_bf16(c[mf][nf], ah[mf], bh);
                    mma_bf16(c[mf][nf], ah[mf], bl);
                    mma_bf16(c[mf][nf], al[mf], bh);
                }
            }
        }
    };

    load_chunk(0, 0);

    for (int m = 0; m < NCHUNK; m++) {
        __syncthreads();                       // stage (m+1)&1 free of compute(m-1) readers
        if (m + 1 < NCHUNK) {
            load_chunk(m + 1, (m + 1) & 1);
            CP_WAIT(1);                        // chunk m landed
        } else {
            CP_WAIT(0);
        }
        __syncthreads();                       // all threads' copies visible
        compute(m & 1);
    }

    // ---- epilogue: fragments -> smem staging (coalesce), then gmem ----
    __syncthreads();
    float* stg = (float*)dsm;   // 128 x 132 fp32 = 67584 B (fits in stage mem)
    #pragma unroll
    for (int mf = 0; mf < 4; mf++) {
        #pragma unroll
        for (int nf = 0; nf < 4; nf++) {
            const int r0 = warp_m * 64 + mf * 16 + (lane >> 2);
            const int cc = warp_n * 32 + nf * 8 + 2 * (lane & 3);
            *(float2*)&stg[(size_t)r0 * 132 + cc]       = make_float2(c[mf][nf][0], c[mf][nf][1]);
            *(float2*)&stg[(size_t)(r0 + 8) * 132 + cc] = make_float2(c[mf][nf][2], c[mf][nf][3]);
        }
    }
    __syncthreads();

    for (int rr = 0; rr < 16; rr++) {
        const int r = wid * 16 + rr;
        const size_t grow = (size_t)(rowBase + r) * HDIM;
        #pragma unroll
        for (int p = 0; p < 4; p++) {
            const int col = p * 32 + lane;
            float v = stg[(size_t)r * 132 + col] + sbias[col];
            const size_t gi = grow + colBase + col;
            if (ADDIN) v += addsrc[gi];
            if (RELU)  v = fmaxf(v, 0.f);
            if (WF32)  outf[gi] = v;
            if (WBF16) {
                __nv_bfloat16 h, l;
                bsplit(v, h, l);
                outhi[gi] = h; outlo[gi] = l;
            }
        }
    }
}

// ---------------------------------------------------------------------------
// Stage C: b = sigmoid(h@Wb^T+bb), g = sigmoid(h@Wg^T+bg)
// ---------------------------------------------------------------------------
__global__ __launch_bounds__(256) void bg_kernel(
    const float* __restrict__ Wb, const float* __restrict__ bbias,
    const float* __restrict__ Wg, const float* __restrict__ gbias)
{
    __shared__ float sWb[HDIM];
    __shared__ float sWg[HDIM];
    const int tid = threadIdx.x;
    for (int i = tid; i < HDIM; i += 256) { sWb[i] = Wb[i]; sWg[i] = Wg[i]; }
    __syncthreads();

    const int warp = tid >> 5;
    const int lane = tid & 31;
    const size_t row = (size_t)blockIdx.x * 8 + warp;
    const float* hr = g_hbuf + row * HDIM;

    float accb = 0.f, accg = 0.f;
    #pragma unroll
    for (int i = 0; i < HDIM / 32; i++) {
        const int idx = lane + i * 32;
        const float hv = hr[idx];
        accb = fmaf(hv, sWb[idx], accb);
        accg = fmaf(hv, sWg[idx], accg);
    }
    #pragma unroll
    for (int o = 16; o; o >>= 1) {
        accb += __shfl_xor_sync(0xFFFFFFFFu, accb, o);
        accg += __shfl_xor_sync(0xFFFFFFFFu, accg, o);
    }
    if (lane == 0) {
        g_bvec[row] = 1.f / (1.f + expf(-(accb + bbias[0])));
        g_gvec[row] = 1.f / (1.f + expf(-(accg + gbias[0])));
    }
}

// ---------------------------------------------------------------------------
// Stage D: SIR reconstruction + 28-step scan
// ---------------------------------------------------------------------------
__global__ __launch_bounds__(256) void sim_kernel(
    const float* __restrict__ x_state, float* __restrict__ out)
{
    const size_t r = (size_t)blockIdx.x * blockDim.x + threadIdx.x;
    const int b = (int)(r >> 11);
    const int n = (int)(r & 2047);

    const float beta = g_bvec[r];
    const float g    = g_gvec[r];
    const float decay = expf(-g);
    const float inv_g = 1.f / g;

    const float* xs = x_state + ((size_t)b * LEN * NNODE + n) * 3;
    const int TSTRIDE = NNODE * 3;

    float Iprev = xs[0 * TSTRIDE + 1];
    float acc = 0.f;
    #pragma unroll
    for (int t = 1; t <= LEN - 1; t++) {
        const float Icur = xs[t * TSTRIDE + 1];
        const float iin = fmaxf((Icur - Iprev) * inv_g + Iprev, 0.f);
        acc = fmaf(acc, decay, iin);
        Iprev = Icur;
    }

    const float Npop  = xs[(LEN - 1) * TSTRIDE + 2];
    const float R_Tm1 = Npop - xs[(LEN - 2) * TSTRIDE + 0];
    const float I_Tm1 = decay * acc;
    const float S_Tm1 = Npop - I_Tm1 - R_Tm1;
    const float Iin0  = beta * S_Tm1 * I_Tm1 / Npop;

    float S = S_Tm1 - Iin0;
    float I = decay * (I_Tm1 + Iin0);

    float* op = out + (size_t)b * LEN * NNODE + n;
    #pragma unroll
    for (int t = 0; t < LEN; t++) {
        const float Iin = beta * S * I / Npop;
        S -= Iin;
        const float Rin = g * I;
        I = decay * (I + Iin);
        op[(size_t)t * NNODE] = Rin;
    }
}

// ---------------------------------------------------------------------------
extern "C" void kernel_launch(void* const* d_in, const int* in_sizes, int n_in,
                              void* d_out, int out_size)
{
    (void)in_sizes; (void)n_in; (void)out_size;
    const float* x_node   = (const float*)d_in[0];
    const float* x_state  = (const float*)d_in[1];
    const float* node_emb = (const float*)d_in[2];
    const float* W_ts     = (const float*)d_in[3];
    const float* b_ts     = (const float*)d_in[4];
    const float* enc_W1   = (const float*)d_in[5];
    const float* enc_b1   = (const float*)d_in[6];
    const float* enc_W2   = (const float*)d_in[7];
    const float* enc_b2   = (const float*)d_in[8];
    const float* Wb       = (const float*)d_in[9];
    const float* bb       = (const float*)d_in[10];
    const float* Wg       = (const float*)d_in[11];
    const float* bg       = (const float*)d_in[12];
    float* out = (float*)d_out;

    float *hbuf = nullptr;
    __nv_bfloat16 *ahi, *alo, *zhi, *zlo, *w1hi, *w1lo, *w2hi, *w2lo;
    cudaGetSymbolAddress((void**)&hbuf, g_hbuf);
    cudaGetSymbolAddress((void**)&ahi, g_ahi);
    cudaGetSymbolAddress((void**)&alo, g_alo);
    cudaGetSymbolAddress((void**)&zhi, g_zhi);
    cudaGetSymbolAddress((void**)&zlo, g_zlo);
    cudaGetSymbolAddress((void**)&w1hi, g_w1hi);
    cudaGetSymbolAddress((void**)&w1lo, g_w1lo);
    cudaGetSymbolAddress((void**)&w2hi, g_w2hi);
    cudaGetSymbolAddress((void**)&w2lo, g_w2lo);

    cudaFuncSetAttribute(gemm_mma<true,  false, false, true >, cudaFuncAttributeMaxDynamicSharedMemorySize, DSMEM);
    cudaFuncSetAttribute(gemm_mma<false, true,  true,  true >, cudaFuncAttributeMaxDynamicSharedMemorySize, DSMEM);
    cudaFuncSetAttribute(gemm_mma<false, true,  true,  false>, cudaFuncAttributeMaxDynamicSharedMemorySize, DSMEM);

    // weights -> bf16 hi/lo
    wconv_kernel<<<(3 * HDIM * HDIM + 255) / 256, 256>>>(enc_W1, enc_W2);

    // Stage A
    ts_kernel<<<MROWS / 64, 256>>>(x_node, node_emb, W_ts, b_ts);

    // Stage B: 3 residual layers on tensor cores (mma.sync)
    const dim3 grid(HDIM / BN, MROWS / BM);   // (4, 512)
    for (int l = 0; l < 3; l++) {
        const __nv_bfloat16* W1h = w1hi + (size_t)l * HDIM * HDIM;
        const __nv_bfloat16* W1l = w1lo + (size_t)l * HDIM * HDIM;
        const __nv_bfloat16* W2h = w2hi + (size_t)l * HDIM * HDIM;
        const __nv_bfloat16* W2l = w2lo + (size_t)l * HDIM * HDIM;
        const float* B1 = enc_b1 + (size_t)l * HDIM;
        const float* B2 = enc_b2 + (size_t)l * HDIM;

        gemm_mma<true, false, false, true><<<grid, 256, DSMEM>>>(
            ahi, alo, W1h, W1l, B1, nullptr, nullptr, zhi, zlo);

        if (l < 2) {
            gemm_mma<false, true, true, true><<<grid, 256, DSMEM>>>(
                zhi, zlo, W2h, W2l, B2, hbuf, hbuf, ahi, alo);
        } else {
            gemm_mma<false, true, true, false><<<grid, 256, DSMEM>>>(
                zhi, zlo, W2h, W2l, B2, hbuf, hbuf, nullptr, nullptr);
        }
    }

    // Stage C + D
    bg_kernel<<<MROWS / 8, 256>>>(Wb, bb, Wg, bg);
    sim_kernel<<<MROWS / 256, 256>>>(x_state, out);
}

// round 5
// speedup vs baseline: 2.1852x; 1.0404x over previous
#include <cuda_runtime.h>
#include <cuda_bf16.h>
#include <math.h>
#include <stdint.h>

// Problem constants
#define BSZ   32
#define LEN   28
#define NNODE 2048
#define EDIM  256
#define HDIM  512
#define MROWS (BSZ*NNODE) // 65536

// GEMM tiling (mma.sync path)
#define BM 128
#define BN 128
#define BK 32
#define NCHUNK (HDIM/BK)    // 16
// XOR-swizzled 64B-pitch stage: 4 arrays of 128 rows x 64 B
#define OAH 0
#define OAL 8192
#define OWH 16384
#define OWL 24576
#define STAGE 32768
#define NSTAGE 3
#define DSMEM (NSTAGE*STAGE) // 98304 -> 2 CTAs/SM

// ---------------------------------------------------------------------------
// Device scratch (no fp32 hbuf anymore: h is always carried as bf16 hi+lo)
// ---------------------------------------------------------------------------
__device__ __nv_bfloat16 g_ahi[(size_t)MROWS * HDIM];   // current h (hi)
__device__ __nv_bfloat16 g_alo[(size_t)MROWS * HDIM];   // current h (lo)
__device__ __nv_bfloat16 g_zhi[(size_t)MROWS * HDIM];
__device__ __nv_bfloat16 g_zlo[(size_t)MROWS * HDIM];
__device__ __nv_bfloat16 g_w1hi[3 * HDIM * HDIM];
__device__ __nv_bfloat16 g_w1lo[3 * HDIM * HDIM];
__device__ __nv_bfloat16 g_w2hi[3 * HDIM * HDIM];
__device__ __nv_bfloat16 g_w2lo[3 * HDIM * HDIM];
__device__ float g_bvec[MROWS];
__device__ float g_gvec[MROWS];

// ---------------------------------------------------------------------------
// PTX helpers (baseline sm_80+ features only)
// ---------------------------------------------------------------------------
__device__ __forceinline__ uint32_t smem_u32(const void* p) {
    uint32_t a;
    asm("{ .reg .u64 t; cvta.to.shared.u64 t, %1; cvt.u32.u64 %0, t; }" : "=r"(a) : "l"(p));
    return a;
}
__device__ __forceinline__ void cp16(uint32_t dst, const void* src) {
    asm volatile("cp.async.cg.shared.global [%0], [%1], 16;" :: "r"(dst), "l"(src));
}
#define CP_COMMIT() asm volatile("cp.async.commit_group;" ::: "memory")
#define CP_WAIT(n)  asm volatile("cp.async.wait_group %0;" :: "n"(n) : "memory")

__device__ __forceinline__ void ldsm_x4(uint32_t r[4], uint32_t addr) {
    asm volatile("ldmatrix.sync.aligned.m8n8.x4.shared.b16 {%0,%1,%2,%3}, [%4];"
        : "=r"(r[0]), "=r"(r[1]), "=r"(r[2]), "=r"(r[3]) : "r"(addr));
}
__device__ __forceinline__ void ldsm_x2(uint32_t r[2], uint32_t addr) {
    asm volatile("ldmatrix.sync.aligned.m8n8.x2.shared.b16 {%0,%1}, [%2];"
        : "=r"(r[0]), "=r"(r[1]) : "r"(addr));
}
__device__ __forceinline__ void mma_bf16(float c[4], const uint32_t a[4], const uint32_t b[2]) {
    asm volatile("mma.sync.aligned.m16n8k16.row.col.f32.bf16.bf16.f32 "
        "{%0,%1,%2,%3}, {%4,%5,%6,%7}, {%8,%9}, {%0,%1,%2,%3};"
        : "+f"(c[0]), "+f"(c[1]), "+f"(c[2]), "+f"(c[3])
        : "r"(a[0]), "r"(a[1]), "r"(a[2]), "r"(a[3]), "r"(b[0]), "r"(b[1]));
}

__device__ __forceinline__ void bsplit(float x, __nv_bfloat16& h, __nv_bfloat16& l) {
    h = __float2bfloat16_rn(x);
    l = __float2bfloat16_rn(x - __bfloat162float(h));
}

// XOR swizzle on 16B units within a 64B-pitch row
__device__ __forceinline__ uint32_t swz(int row, int q) {
    return (uint32_t)(row * 64 + ((q ^ (row & 3)) << 4));
}

// ---------------------------------------------------------------------------
// Weight conversion: fp32 -> bf16 hi/lo
// ---------------------------------------------------------------------------
__global__ __launch_bounds__(256) void wconv_kernel(const float* __restrict__ W1,
                                                    const float* __restrict__ W2)
{
    const int i = blockIdx.x * 256 + threadIdx.x;
    if (i >= 3 * HDIM * HDIM) return;
    __nv_bfloat16 h, l;
    bsplit(W1[i], h, l); g_w1hi[i] = h; g_w1lo[i] = l;
    bsplit(W2[i], h, l); g_w2hi[i] = h; g_w2lo[i] = l;
}

// ---------------------------------------------------------------------------
// Stage A: ts GEMM (K=28) + concat node_emb ; writes bf16 hi/lo h
// ---------------------------------------------------------------------------
__global__ __launch_bounds__(256) void ts_kernel(
    const float* __restrict__ x_node,
    const float* __restrict__ node_emb,
    const float* __restrict__ W_ts,
    const float* __restrict__ b_ts)
{
    __shared__ float sW[EDIM * LEN];
    __shared__ float sF[64 * LEN];

    const int rowBase = blockIdx.x * 64;
    const int bidx  = rowBase >> 11;
    const int nBase = rowBase & 2047;
    const int tid = threadIdx.x;

    for (int i = tid; i < EDIM * LEN; i += 256) sW[i] = W_ts[i];
    for (int idx = tid; idx < 64 * LEN; idx += 256) {
        int l = idx >> 6;
        int i = idx & 63;
        sF[i * LEN + l] = x_node[((size_t)(bidx * LEN + l)) * NNODE + nBase + i];
    }
    __syncthreads();

    const int e = tid;
    const float bias = b_ts[e];
    const float* wrow = &sW[e * LEN];

    for (int i = 0; i < 64; i++) {
        float acc = bias;
        #pragma unroll
        for (int l = 0; l < LEN; l++)
            acc = fmaf(sF[i * LEN + l], wrow[l], acc);
        const size_t r = (size_t)(rowBase + i) * HDIM;
        const float ne = node_emb[(size_t)(nBase + i) * EDIM + e];
        __nv_bfloat16 h, l;
        bsplit(acc, h, l); g_ahi[r + e] = h;        g_alo[r + e] = l;
        bsplit(ne, h, l);  g_ahi[r + EDIM + e] = h; g_alo[r + EDIM + e] = l;
    }
}

// ---------------------------------------------------------------------------
// bf16x3 split GEMM on mma.sync: C = A @ W^T + bias [+ (Rhi+Rlo)] [relu]
// 3-stage cp.async multistage (one __syncthreads per chunk), XOR swizzle.
// Output written as bf16 hi/lo split only.
// ---------------------------------------------------------------------------
template <bool RELU, bool ADDIN>
__global__ void __launch_bounds__(256, 2) gemm_mma(
    const __nv_bfloat16* __restrict__ Ahi, const __nv_bfloat16* __restrict__ Alo,
    const __nv_bfloat16* __restrict__ Whi, const __nv_bfloat16* __restrict__ Wlo,
    const float* __restrict__ bias,
    const __nv_bfloat16* __restrict__ Rhi, const __nv_bfloat16* __restrict__ Rlo,
    __nv_bfloat16* __restrict__ outhi, __nv_bfloat16* __restrict__ outlo)
{
    extern __shared__ char dsm[];
    __shared__ float sbias[BN];

    const int tid = threadIdx.x;
    const int wid = tid >> 5;
    const int lane = tid & 31;
    const int warp_m = wid & 1;
    const int warp_n = wid >> 1;
    const int rowBase = blockIdx.y * BM;
    const int colBase = blockIdx.x * BN;

    if (tid < BN) sbias[tid] = bias[colBase + tid];

    const uint32_t sb = smem_u32(dsm);

    float c[4][4][4];
    #pragma unroll
    for (int i = 0; i < 4; i++)
        #pragma unroll
        for (int j = 0; j < 4; j++)
            #pragma unroll
            for (int k = 0; k < 4; k++) c[i][j][k] = 0.f;

    // ---- chunk loader: 512 16B-chunks per array, 2 per thread ----
    auto load_chunk = [&](int cidx, int s) {
        const uint32_t base = sb + (uint32_t)s * STAGE;
        const int kk = cidx * BK;
        #pragma unroll
        for (int j = 0; j < 2; j++) {
            const int ch = tid * 2 + j;
            const int row = ch >> 2;
            const int q = ch & 3;
            const uint32_t doff = swz(row, q);
            const int eoff = kk + q * 8;       // 8 bf16 per 16B
            cp16(base + OAH + doff, Ahi + (size_t)(rowBase + row) * HDIM + eoff);
            cp16(base + OAL + doff, Alo + (size_t)(rowBase + row) * HDIM + eoff);
            cp16(base + OWH + doff, Whi + (size_t)(colBase + row) * HDIM + eoff);
            cp16(base + OWL + doff, Wlo + (size_t)(colBase + row) * HDIM + eoff);
        }
        CP_COMMIT();
    };

    // ---- per-stage compute: 2 k16 steps ----
    const int ra = warp_m * 64 + (lane & 15);
    const int rb = warp_n * 32 + (lane & 7);
    const int qa_bit = (lane >> 4);
    const int qb_bit = ((lane >> 3) & 1);

    auto compute = [&](int s) {
        const uint32_t base = sb + (uint32_t)s * STAGE;
        #pragma unroll
        for (int ks = 0; ks < 2; ks++) {
            const uint32_t aoff = swz(ra, qa_bit + 2 * ks);
            const uint32_t boff = swz(rb, qb_bit + 2 * ks);
            uint32_t ah[4][4], al[4][4];
            #pragma unroll
            for (int mf = 0; mf < 4; mf++) {
                ldsm_x4(ah[mf], base + OAH + aoff + (uint32_t)(mf * 1024));
                ldsm_x4(al[mf], base + OAL + aoff + (uint32_t)(mf * 1024));
            }
            #pragma unroll
            for (int nf = 0; nf < 4; nf++) {
                uint32_t bh[2], bl[2];
                ldsm_x2(bh, base + OWH + boff + (uint32_t)(nf * 512));
                ldsm_x2(bl, base + OWL + boff + (uint32_t)(nf * 512));
                #pragma unroll
                for (int mf = 0; mf < 4; mf++) {
                    mma_bf16(c[mf][nf], ah[mf], bh);
                    mma_bf16(c[mf][nf], ah[mf], bl);
                    mma_bf16(c[mf][nf], al[mf], bh);
                }
            }
        }
    };

    // ---- multistage mainloop: 1 sync per chunk ----
    load_chunk(0, 0);
    load_chunk(1, 1);
    CP_WAIT(1);            // chunk 0 landed
    __syncthreads();

    for (int m = 0; m < NCHUNK; m++) {
        if (m + 2 < NCHUNK) load_chunk(m + 2, (m + 2) % NSTAGE);
        compute(m % NSTAGE);
        if (m + 2 < NCHUNK)      { CP_WAIT(1); }   // chunk m+1 landed
        else if (m + 1 < NCHUNK) { CP_WAIT(0); }
        __syncthreads();
    }

    // ---- epilogue: fragments -> smem staging (coalesce), then gmem ----
    float* stg = (float*)dsm;   // 128 x 132 fp32 = 67584 B
    #pragma unroll
    for (int mf = 0; mf < 4; mf++) {
        #pragma unroll
        for (int nf = 0; nf < 4; nf++) {
            const int r0 = warp_m * 64 + mf * 16 + (lane >> 2);
            const int cc = warp_n * 32 + nf * 8 + 2 * (lane & 3);
            *(float2*)&stg[(size_t)r0 * 132 + cc]       = make_float2(c[mf][nf][0], c[mf][nf][1]);
            *(float2*)&stg[(size_t)(r0 + 8) * 132 + cc] = make_float2(c[mf][nf][2], c[mf][nf][3]);
        }
    }
    __syncthreads();

    for (int rr = 0; rr < 16; rr++) {
        const int r = wid * 16 + rr;
        const size_t grow = (size_t)(rowBase + r) * HDIM;
        #pragma unroll
        for (int p = 0; p < 4; p++) {
            const int col = p * 32 + lane;
            float v = stg[(size_t)r * 132 + col] + sbias[col];
            const size_t gi = grow + colBase + col;
            if (ADDIN)
                v += __bfloat162float(Rhi[gi]) + __bfloat162float(Rlo[gi]);
            if (RELU) v = fmaxf(v, 0.f);
            __nv_bfloat16 h, l;
            bsplit(v, h, l);
            outhi[gi] = h; outlo[gi] = l;
        }
    }
}

// ---------------------------------------------------------------------------
// Stage C: b = sigmoid(h@Wb^T+bb), g = sigmoid(h@Wg^T+bg); h = hi+lo
// ---------------------------------------------------------------------------
__global__ __launch_bounds__(256) void bg_kernel(
    const float* __restrict__ Wb, const float* __restrict__ bbias,
    const float* __restrict__ Wg, const float* __restrict__ gbias)
{
    __shared__ float sWb[HDIM];
    __shared__ float sWg[HDIM];
    const int tid = threadIdx.x;
    for (int i = tid; i < HDIM; i += 256) { sWb[i] = Wb[i]; sWg[i] = Wg[i]; }
    __syncthreads();

    const int warp = tid >> 5;
    const int lane = tid & 31;
    const size_t row = (size_t)blockIdx.x * 8 + warp;
    const __nv_bfloat16* hh = g_ahi + row * HDIM;
    const __nv_bfloat16* hl = g_alo + row * HDIM;

    float accb = 0.f, accg = 0.f;
    #pragma unroll
    for (int i = 0; i < HDIM / 32; i++) {
        const int idx = lane + i * 32;
        const float hv = __bfloat162float(hh[idx]) + __bfloat162float(hl[idx]);
        accb = fmaf(hv, sWb[idx], accb);
        accg = fmaf(hv, sWg[idx], accg);
    }
    #pragma unroll
    for (int o = 16; o; o >>= 1) {
        accb += __shfl_xor_sync(0xFFFFFFFFu, accb, o);
        accg += __shfl_xor_sync(0xFFFFFFFFu, accg, o);
    }
    if (lane == 0) {
        g_bvec[row] = 1.f / (1.f + expf(-(accb + bbias[0])));
        g_gvec[row] = 1.f / (1.f + expf(-(accg + gbias[0])));
    }
}

// ---------------------------------------------------------------------------
// Stage D: SIR reconstruction + 28-step scan
// ---------------------------------------------------------------------------
__global__ __launch_bounds__(256) void sim_kernel(
    const float* __restrict__ x_state, float* __restrict__ out)
{
    const size_t r = (size_t)blockIdx.x * blockDim.x + threadIdx.x;
    const int b = (int)(r >> 11);
    const int n = (int)(r & 2047);

    const float beta = g_bvec[r];
    const float g    = g_gvec[r];
    const float decay = expf(-g);
    const float inv_g = 1.f / g;

    const float* xs = x_state + ((size_t)b * LEN * NNODE + n) * 3;
    const int TSTRIDE = NNODE * 3;

    float Iprev = xs[0 * TSTRIDE + 1];
    float acc = 0.f;
    #pragma unroll
    for (int t = 1; t <= LEN - 1; t++) {
        const float Icur = xs[t * TSTRIDE + 1];
        const float iin = fmaxf((Icur - Iprev) * inv_g + Iprev, 0.f);
        acc = fmaf(acc, decay, iin);
        Iprev = Icur;
    }

    const float Npop  = xs[(LEN - 1) * TSTRIDE + 2];
    const float R_Tm1 = Npop - xs[(LEN - 2) * TSTRIDE + 0];
    const float I_Tm1 = decay * acc;
    const float S_Tm1 = Npop - I_Tm1 - R_Tm1;
    const float Iin0  = beta * S_Tm1 * I_Tm1 / Npop;

    float S = S_Tm1 - Iin0;
    float I = decay * (I_Tm1 + Iin0);

    float* op = out + (size_t)b * LEN * NNODE + n;
    #pragma unroll
    for (int t = 0; t < LEN; t++) {
        const float Iin = beta * S * I / Npop;
        S -= Iin;
        const float Rin = g * I;
        I = decay * (I + Iin);
        op[(size_t)t * NNODE] = Rin;
    }
}

// ---------------------------------------------------------------------------
extern "C" void kernel_launch(void* const* d_in, const int* in_sizes, int n_in,
                              void* d_out, int out_size)
{
    (void)in_sizes; (void)n_in; (void)out_size;
    const float* x_node   = (const float*)d_in[0];
    const float* x_state  = (const float*)d_in[1];
    const float* node_emb = (const float*)d_in[2];
    const float* W_ts     = (const float*)d_in[3];
    const float* b_ts     = (const float*)d_in[4];
    const float* enc_W1   = (const float*)d_in[5];
    const float* enc_b1   = (const float*)d_in[6];
    const float* enc_W2   = (const float*)d_in[7];
    const float* enc_b2   = (const float*)d_in[8];
    const float* Wb       = (const float*)d_in[9];
    const float* bb       = (const float*)d_in[10];
    const float* Wg       = (const float*)d_in[11];
    const float* bg       = (const float*)d_in[12];
    float* out = (float*)d_out;

    __nv_bfloat16 *ahi, *alo, *zhi, *zlo, *w1hi, *w1lo, *w2hi, *w2lo;
    cudaGetSymbolAddress((void**)&ahi, g_ahi);
    cudaGetSymbolAddress((void**)&alo, g_alo);
    cudaGetSymbolAddress((void**)&zhi, g_zhi);
    cudaGetSymbolAddress((void**)&zlo, g_zlo);
    cudaGetSymbolAddress((void**)&w1hi, g_w1hi);
    cudaGetSymbolAddress((void**)&w1lo, g_w1lo);
    cudaGetSymbolAddress((void**)&w2hi, g_w2hi);
    cudaGetSymbolAddress((void**)&w2lo, g_w2lo);

    cudaFuncSetAttribute(gemm_mma<true,  false>, cudaFuncAttributeMaxDynamicSharedMemorySize, DSMEM);
    cudaFuncSetAttribute(gemm_mma<false, true >, cudaFuncAttributeMaxDynamicSharedMemorySize, DSMEM);

    // weights -> bf16 hi/lo
    wconv_kernel<<<(3 * HDIM * HDIM + 255) / 256, 256>>>(enc_W1, enc_W2);

    // Stage A
    ts_kernel<<<MROWS / 64, 256>>>(x_node, node_emb, W_ts, b_ts);

    // Stage B: 3 residual layers on tensor cores (mma.sync)
    const dim3 grid(HDIM / BN, MROWS / BM);   // (4, 512)
    for (int l = 0; l < 3; l++) {
        const __nv_bfloat16* W1h = w1hi + (size_t)l * HDIM * HDIM;
        const __nv_bfloat16* W1l = w1lo + (size_t)l * HDIM * HDIM;
        const __nv_bfloat16* W2h = w2hi + (size_t)l * HDIM * HDIM;
        const __nv_bfloat16* W2l = w2lo + (size_t)l * HDIM * HDIM;
        const float* B1 = enc_b1 + (size_t)l * HDIM;
        const float* B2 = enc_b2 + (size_t)l * HDIM;

        // z = relu(h @ W1^T + b1)
        gemm_mma<true, false><<<grid, 256, DSMEM>>>(
            ahi, alo, W1h, W1l, B1, nullptr, nullptr, zhi, zlo);
        // h = h + z @ W2^T + b2   (in-place hi/lo update)
        gemm_mma<false, true><<<grid, 256, DSMEM>>>(
            zhi, zlo, W2h, W2l, B2, ahi, alo, ahi, alo);
    }

    // Stage C + D
    bg_kernel<<<MROWS / 8, 256>>>(Wb, bb, Wg, bg);
    sim_kernel<<<MROWS / 256, 256>>>(x_state, out);
}

// round 6
// speedup vs baseline: 2.3979x; 1.0973x over previous
#include <cuda_runtime.h>
#include <cuda_bf16.h>
#include <math.h>
#include <stdint.h>

// Problem constants
#define BSZ   32
#define LEN   28
#define NNODE 2048
#define EDIM  256
#define HDIM  512
#define MROWS (BSZ*NNODE) // 65536

// GEMM tiling (mma.sync path)
#define BM 128
#define BN 128
#define BK 32
#define NCHUNK (HDIM/BK)    // 16
// XOR-swizzled 64B-pitch stage: 4 arrays of 128 rows x 64 B
#define OAH 0
#define OAL 8192
#define OWH 16384
#define OWL 24576
#define STAGE 32768
#define NSTAGE 3
#define DSMEM (NSTAGE*STAGE) // 98304 -> 2 CTAs/SM

// ---------------------------------------------------------------------------
// Device scratch (h carried as bf16 hi+lo everywhere)
// ---------------------------------------------------------------------------
__device__ __nv_bfloat16 g_ahi[(size_t)MROWS * HDIM];
__device__ __nv_bfloat16 g_alo[(size_t)MROWS * HDIM];
__device__ __nv_bfloat16 g_zhi[(size_t)MROWS * HDIM];
__device__ __nv_bfloat16 g_zlo[(size_t)MROWS * HDIM];
__device__ __nv_bfloat16 g_w1hi[3 * HDIM * HDIM];
__device__ __nv_bfloat16 g_w1lo[3 * HDIM * HDIM];
__device__ __nv_bfloat16 g_w2hi[3 * HDIM * HDIM];
__device__ __nv_bfloat16 g_w2lo[3 * HDIM * HDIM];
__device__ float g_bvec[MROWS];
__device__ float g_gvec[MROWS];

// ---------------------------------------------------------------------------
// PTX helpers (baseline sm_80+ features only)
// ---------------------------------------------------------------------------
__device__ __forceinline__ uint32_t smem_u32(const void* p) {
    uint32_t a;
    asm("{ .reg .u64 t; cvta.to.shared.u64 t, %1; cvt.u32.u64 %0, t; }" : "=r"(a) : "l"(p));
    return a;
}
__device__ __forceinline__ void cp16(uint32_t dst, const void* src) {
    asm volatile("cp.async.cg.shared.global [%0], [%1], 16;" :: "r"(dst), "l"(src));
}
#define CP_COMMIT() asm volatile("cp.async.commit_group;" ::: "memory")
#define CP_WAIT(n)  asm volatile("cp.async.wait_group %0;" :: "n"(n) : "memory")

__device__ __forceinline__ void ldsm_x4(uint32_t r[4], uint32_t addr) {
    asm volatile("ldmatrix.sync.aligned.m8n8.x4.shared.b16 {%0,%1,%2,%3}, [%4];"
        : "=r"(r[0]), "=r"(r[1]), "=r"(r[2]), "=r"(r[3]) : "r"(addr));
}
__device__ __forceinline__ void mma_bf16(float c[4], const uint32_t a[4], const uint32_t b[2]) {
    asm volatile("mma.sync.aligned.m16n8k16.row.col.f32.bf16.bf16.f32 "
        "{%0,%1,%2,%3}, {%4,%5,%6,%7}, {%8,%9}, {%0,%1,%2,%3};"
        : "+f"(c[0]), "+f"(c[1]), "+f"(c[2]), "+f"(c[3])
        : "r"(a[0]), "r"(a[1]), "r"(a[2]), "r"(a[3]), "r"(b[0]), "r"(b[1]));
}

__device__ __forceinline__ void bsplit(float x, __nv_bfloat16& h, __nv_bfloat16& l) {
    h = __float2bfloat16_rn(x);
    l = __float2bfloat16_rn(x - __bfloat162float(h));
}

// Conflict-free XOR swizzle on 16B units within a 64B-pitch row.
// chunk' = q ^ ((row>>1)&3); with the (row&1)*64 alternation this maps the
// 8 rows of any ldmatrix phase onto 8 distinct 16B slots mod 128B.
__device__ __forceinline__ uint32_t swz(int row, int q) {
    return (uint32_t)(row * 64 + ((q ^ ((row >> 1) & 3)) << 4));
}

// ---------------------------------------------------------------------------
// Weight conversion: fp32 -> bf16 hi/lo
// ---------------------------------------------------------------------------
__global__ __launch_bounds__(256) void wconv_kernel(const float* __restrict__ W1,
                                                    const float* __restrict__ W2)
{
    const int i = blockIdx.x * 256 + threadIdx.x;
    if (i >= 3 * HDIM * HDIM) return;
    __nv_bfloat16 h, l;
    bsplit(W1[i], h, l); g_w1hi[i] = h; g_w1lo[i] = l;
    bsplit(W2[i], h, l); g_w2hi[i] = h; g_w2lo[i] = l;
}

// ---------------------------------------------------------------------------
// Stage A: ts GEMM (K=28) + concat node_emb ; writes bf16 hi/lo h
// ---------------------------------------------------------------------------
__global__ __launch_bounds__(256) void ts_kernel(
    const float* __restrict__ x_node,
    const float* __restrict__ node_emb,
    const float* __restrict__ W_ts,
    const float* __restrict__ b_ts)
{
    __shared__ float sW[EDIM * LEN];
    __shared__ float sF[64 * LEN];

    const int rowBase = blockIdx.x * 64;
    const int bidx  = rowBase >> 11;
    const int nBase = rowBase & 2047;
    const int tid = threadIdx.x;

    for (int i = tid; i < EDIM * LEN; i += 256) sW[i] = W_ts[i];
    for (int idx = tid; idx < 64 * LEN; idx += 256) {
        int l = idx >> 6;
        int i = idx & 63;
        sF[i * LEN + l] = x_node[((size_t)(bidx * LEN + l)) * NNODE + nBase + i];
    }
    __syncthreads();

    const int e = tid;
    const float bias = b_ts[e];
    const float* wrow = &sW[e * LEN];

    for (int i = 0; i < 64; i++) {
        float acc = bias;
        #pragma unroll
        for (int l = 0; l < LEN; l++)
            acc = fmaf(sF[i * LEN + l], wrow[l], acc);
        const size_t r = (size_t)(rowBase + i) * HDIM;
        const float ne = node_emb[(size_t)(nBase + i) * EDIM + e];
        __nv_bfloat16 h, l;
        bsplit(acc, h, l); g_ahi[r + e] = h;        g_alo[r + e] = l;
        bsplit(ne, h, l);  g_ahi[r + EDIM + e] = h; g_alo[r + EDIM + e] = l;
    }
}

// ---------------------------------------------------------------------------
// bf16x3 split GEMM on mma.sync: C = A @ W^T + bias [+ (Rhi+Rlo)] [relu]
// 3-stage cp.async multistage, conflict-free swizzle, B frags via ldsm.x4,
// A frags register-double-buffered across mf.
// ---------------------------------------------------------------------------
template <bool RELU, bool ADDIN>
__global__ void __launch_bounds__(256, 2) gemm_mma(
    const __nv_bfloat16* __restrict__ Ahi, const __nv_bfloat16* __restrict__ Alo,
    const __nv_bfloat16* __restrict__ Whi, const __nv_bfloat16* __restrict__ Wlo,
    const float* __restrict__ bias,
    const __nv_bfloat16* __restrict__ Rhi, const __nv_bfloat16* __restrict__ Rlo,
    __nv_bfloat16* __restrict__ outhi, __nv_bfloat16* __restrict__ outlo)
{
    extern __shared__ char dsm[];
    __shared__ float sbias[BN];

    const int tid = threadIdx.x;
    const int wid = tid >> 5;
    const int lane = tid & 31;
    const int warp_m = wid & 1;
    const int warp_n = wid >> 1;
    const int rowBase = blockIdx.y * BM;
    const int colBase = blockIdx.x * BN;

    if (tid < BN) sbias[tid] = bias[colBase + tid];

    const uint32_t sb = smem_u32(dsm);

    float c[4][4][4];
    #pragma unroll
    for (int i = 0; i < 4; i++)
        #pragma unroll
        for (int j = 0; j < 4; j++)
            #pragma unroll
            for (int k = 0; k < 4; k++) c[i][j][k] = 0.f;

    // ---- chunk loader: 512 16B-chunks per array, 2 per thread ----
    auto load_chunk = [&](int cidx, int s) {
        const uint32_t base = sb + (uint32_t)s * STAGE;
        const int kk = cidx * BK;
        #pragma unroll
        for (int j = 0; j < 2; j++) {
            const int ch = tid * 2 + j;
            const int row = ch >> 2;
            const int q = ch & 3;
            const uint32_t doff = swz(row, q);
            const int eoff = kk + q * 8;       // 8 bf16 per 16B
            cp16(base + OAH + doff, Ahi + (size_t)(rowBase + row) * HDIM + eoff);
            cp16(base + OAL + doff, Alo + (size_t)(rowBase + row) * HDIM + eoff);
            cp16(base + OWH + doff, Whi + (size_t)(colBase + row) * HDIM + eoff);
            cp16(base + OWL + doff, Wlo + (size_t)(colBase + row) * HDIM + eoff);
        }
        CP_COMMIT();
    };

    // ---- fragment addressing ----
    // A (x4): lanes 0-15 -> 16 m-rows @ k-half0, lanes 16-31 same rows @ k-half1
    const int ra  = warp_m * 64 + (lane & 15);
    const int qa  = lane >> 4;
    // B (x4, nf-pair): lanes 0-7 rows(nf even) khalf0, 8-15 khalf1,
    //                  16-23 rows(nf odd) khalf0, 24-31 khalf1
    const int rb  = warp_n * 32 + ((lane >> 4) & 1) * 8 + (lane & 7);
    const int qb  = (lane >> 3) & 1;

    auto compute = [&](int s) {
        const uint32_t base = sb + (uint32_t)s * STAGE;
        #pragma unroll
        for (int ks = 0; ks < 2; ks++) {
            // B fragments for all 4 nf (hi and lo): 4 x ldsm_x4
            uint32_t bh[2][4], bl[2][4];
            #pragma unroll
            for (int p = 0; p < 2; p++) {
                const uint32_t boff = swz(rb + p * 16, qb + 2 * ks);
                ldsm_x4(bh[p], base + OWH + boff);
                ldsm_x4(bl[p], base + OWL + boff);
            }
            // A fragments streamed per-mf with 1-deep double buffer
            const uint32_t aoff = swz(ra, qa + 2 * ks);
            uint32_t ah[2][4], al[2][4];
            ldsm_x4(ah[0], base + OAH + aoff);
            ldsm_x4(al[0], base + OAL + aoff);
            #pragma unroll
            for (int mf = 0; mf < 4; mf++) {
                const int cur = mf & 1, nxt = cur ^ 1;
                if (mf < 3) {
                    ldsm_x4(ah[nxt], base + OAH + aoff + (uint32_t)((mf + 1) * 1024));
                    ldsm_x4(al[nxt], base + OAL + aoff + (uint32_t)((mf + 1) * 1024));
                }
                #pragma unroll
                for (int nf = 0; nf < 4; nf++)
                    mma_bf16(c[mf][nf], ah[cur], &bh[nf >> 1][(nf & 1) * 2]);
                #pragma unroll
                for (int nf = 0; nf < 4; nf++)
                    mma_bf16(c[mf][nf], ah[cur], &bl[nf >> 1][(nf & 1) * 2]);
                #pragma unroll
                for (int nf = 0; nf < 4; nf++)
                    mma_bf16(c[mf][nf], al[cur], &bh[nf >> 1][(nf & 1) * 2]);
            }
        }
    };

    // ---- multistage mainloop: 1 sync per chunk ----
    load_chunk(0, 0);
    load_chunk(1, 1);
    CP_WAIT(1);            // chunk 0 landed
    __syncthreads();

    for (int m = 0; m < NCHUNK; m++) {
        if (m + 2 < NCHUNK) load_chunk(m + 2, (m + 2) % NSTAGE);
        compute(m % NSTAGE);
        if (m + 2 < NCHUNK)      { CP_WAIT(1); }   // chunk m+1 landed
        else if (m + 1 < NCHUNK) { CP_WAIT(0); }
        __syncthreads();
    }

    // ---- epilogue: fragments -> smem staging (coalesce), then gmem ----
    float* stg = (float*)dsm;   // 128 x 132 fp32 = 67584 B
    #pragma unroll
    for (int mf = 0; mf < 4; mf++) {
        #pragma unroll
        for (int nf = 0; nf < 4; nf++) {
            const int r0 = warp_m * 64 + mf * 16 + (lane >> 2);
            const int cc = warp_n * 32 + nf * 8 + 2 * (lane & 3);
            *(float2*)&stg[(size_t)r0 * 132 + cc]       = make_float2(c[mf][nf][0], c[mf][nf][1]);
            *(float2*)&stg[(size_t)(r0 + 8) * 132 + cc] = make_float2(c[mf][nf][2], c[mf][nf][3]);
        }
    }
    __syncthreads();

    for (int rr = 0; rr < 16; rr++) {
        const int r = wid * 16 + rr;
        const size_t grow = (size_t)(rowBase + r) * HDIM;
        #pragma unroll
        for (int p = 0; p < 4; p++) {
            const int col = p * 32 + lane;
            float v = stg[(size_t)r * 132 + col] + sbias[col];
            const size_t gi = grow + colBase + col;
            if (ADDIN)
                v += __bfloat162float(Rhi[gi]) + __bfloat162float(Rlo[gi]);
            if (RELU) v = fmaxf(v, 0.f);
            __nv_bfloat16 h, l;
            bsplit(v, h, l);
            outhi[gi] = h; outlo[gi] = l;
        }
    }
}

// ---------------------------------------------------------------------------
// Stage C: b = sigmoid(h@Wb^T+bb), g = sigmoid(h@Wg^T+bg); h = hi+lo
// ---------------------------------------------------------------------------
__global__ __launch_bounds__(256) void bg_kernel(
    const float* __restrict__ Wb, const float* __restrict__ bbias,
    const float* __restrict__ Wg, const float* __restrict__ gbias)
{
    __shared__ float sWb[HDIM];
    __shared__ float sWg[HDIM];
    const int tid = threadIdx.x;
    for (int i = tid; i < HDIM; i += 256) { sWb[i] = Wb[i]; sWg[i] = Wg[i]; }
    __syncthreads();

    const int warp = tid >> 5;
    const int lane = tid & 31;
    const size_t row = (size_t)blockIdx.x * 8 + warp;
    const __nv_bfloat16* hh = g_ahi + row * HDIM;
    const __nv_bfloat16* hl = g_alo + row * HDIM;

    float accb = 0.f, accg = 0.f;
    #pragma unroll
    for (int i = 0; i < HDIM / 32; i++) {
        const int idx = lane + i * 32;
        const float hv = __bfloat162float(hh[idx]) + __bfloat162float(hl[idx]);
        accb = fmaf(hv, sWb[idx], accb);
        accg = fmaf(hv, sWg[idx], accg);
    }
    #pragma unroll
    for (int o = 16; o; o >>= 1) {
        accb += __shfl_xor_sync(0xFFFFFFFFu, accb, o);
        accg += __shfl_xor_sync(0xFFFFFFFFu, accg, o);
    }
    if (lane == 0) {
        g_bvec[row] = 1.f / (1.f + expf(-(accb + bbias[0])));
        g_gvec[row] = 1.f / (1.f + expf(-(accg + gbias[0])));
    }
}

// ---------------------------------------------------------------------------
// Stage D: SIR reconstruction + 28-step scan
// ---------------------------------------------------------------------------
__global__ __launch_bounds__(256) void sim_kernel(
    const float* __restrict__ x_state, float* __restrict__ out)
{
    const size_t r = (size_t)blockIdx.x * blockDim.x + threadIdx.x;
    const int b = (int)(r >> 11);
    const int n = (int)(r & 2047);

    const float beta = g_bvec[r];
    const float g    = g_gvec[r];
    const float decay = expf(-g);
    const float inv_g = 1.f / g;

    const float* xs = x_state + ((size_t)b * LEN * NNODE + n) * 3;
    const int TSTRIDE = NNODE * 3;

    float Iprev = xs[0 * TSTRIDE + 1];
    float acc = 0.f;
    #pragma unroll
    for (int t = 1; t <= LEN - 1; t++) {
        const float Icur = xs[t * TSTRIDE + 1];
        const float iin = fmaxf((Icur - Iprev) * inv_g + Iprev, 0.f);
        acc = fmaf(acc, decay, iin);
        Iprev = Icur;
    }

    const float Npop  = xs[(LEN - 1) * TSTRIDE + 2];
    const float R_Tm1 = Npop - xs[(LEN - 2) * TSTRIDE + 0];
    const float I_Tm1 = decay * acc;
    const float S_Tm1 = Npop - I_Tm1 - R_Tm1;
    const float Iin0  = beta * S_Tm1 * I_Tm1 / Npop;

    float S = S_Tm1 - Iin0;
    float I = decay * (I_Tm1 + Iin0);

    float* op = out + (size_t)b * LEN * NNODE + n;
    #pragma unroll
    for (int t = 0; t < LEN; t++) {
        const float Iin = beta * S * I / Npop;
        S -= Iin;
        const float Rin = g * I;
        I = decay * (I + Iin);
        op[(size_t)t * NNODE] = Rin;
    }
}

// ---------------------------------------------------------------------------
extern "C" void kernel_launch(void* const* d_in, const int* in_sizes, int n_in,
                              void* d_out, int out_size)
{
    (void)in_sizes; (void)n_in; (void)out_size;
    const float* x_node   = (const float*)d_in[0];
    const float* x_state  = (const float*)d_in[1];
    const float* node_emb = (const float*)d_in[2];
    const float* W_ts     = (const float*)d_in[3];
    const float* b_ts     = (const float*)d_in[4];
    const float* enc_W1   = (const float*)d_in[5];
    const float* enc_b1   = (const float*)d_in[6];
    const float* enc_W2   = (const float*)d_in[7];
    const float* enc_b2   = (const float*)d_in[8];
    const float* Wb       = (const float*)d_in[9];
    const float* bb       = (const float*)d_in[10];
    const float* Wg       = (const float*)d_in[11];
    const float* bg       = (const float*)d_in[12];
    float* out = (float*)d_out;

    __nv_bfloat16 *ahi, *alo, *zhi, *zlo, *w1hi, *w1lo, *w2hi, *w2lo;
    cudaGetSymbolAddress((void**)&ahi, g_ahi);
    cudaGetSymbolAddress((void**)&alo, g_alo);
    cudaGetSymbolAddress((void**)&zhi, g_zhi);
    cudaGetSymbolAddress((void**)&zlo, g_zlo);
    cudaGetSymbolAddress((void**)&w1hi, g_w1hi);
    cudaGetSymbolAddress((void**)&w1lo, g_w1lo);
    cudaGetSymbolAddress((void**)&w2hi, g_w2hi);
    cudaGetSymbolAddress((void**)&w2lo, g_w2lo);

    cudaFuncSetAttribute(gemm_mma<true,  false>, cudaFuncAttributeMaxDynamicSharedMemorySize, DSMEM);
    cudaFuncSetAttribute(gemm_mma<false, true >, cudaFuncAttributeMaxDynamicSharedMemorySize, DSMEM);

    // weights -> bf16 hi/lo
    wconv_kernel<<<(3 * HDIM * HDIM + 255) / 256, 256>>>(enc_W1, enc_W2);

    // Stage A
    ts_kernel<<<MROWS / 64, 256>>>(x_node, node_emb, W_ts, b_ts);

    // Stage B: 3 residual layers on tensor cores (mma.sync)
    const dim3 grid(HDIM / BN, MROWS / BM);   // (4, 512)
    for (int l = 0; l < 3; l++) {
        const __nv_bfloat16* W1h = w1hi + (size_t)l * HDIM * HDIM;
        const __nv_bfloat16* W1l = w1lo + (size_t)l * HDIM * HDIM;
        const __nv_bfloat16* W2h = w2hi + (size_t)l * HDIM * HDIM;
        const __nv_bfloat16* W2l = w2lo + (size_t)l * HDIM * HDIM;
        const float* B1 = enc_b1 + (size_t)l * HDIM;
        const float* B2 = enc_b2 + (size_t)l * HDIM;

        // z = relu(h @ W1^T + b1)
        gemm_mma<true, false><<<grid, 256, DSMEM>>>(
            ahi, alo, W1h, W1l, B1, nullptr, nullptr, zhi, zlo);
        // h = h + z @ W2^T + b2   (in-place hi/lo update)
        gemm_mma<false, true><<<grid, 256, DSMEM>>>(
            zhi, zlo, W2h, W2l, B2, ahi, alo, ahi, alo);
    }

    // Stage C + D
    bg_kernel<<<MROWS / 8, 256>>>(Wb, bb, Wg, bg);
    sim_kernel<<<MROWS / 256, 256>>>(x_state, out);
}

// round 7
// speedup vs baseline: 3.1915x; 1.3310x over previous
#include <cuda_runtime.h>
#include <cuda_fp16.h>
#include <math.h>
#include <stdint.h>

// Problem constants
#define BSZ   32
#define LEN   28
#define NNODE 2048
#define EDIM  256
#define HDIM  512
#define MROWS (BSZ*NNODE) // 65536

// GEMM tiling (mma.sync fp16 2-term path)
#define BM 128
#define BN 128
#define BK 32
#define NCHUNK (HDIM/BK)    // 16
// XOR-swizzled 64B-pitch stage: 3 arrays (A, Whi, Wlo) of 128 rows x 64 B
#define OA  0
#define OWH 8192
#define OWL 16384
#define STAGE 24576
#define NSTAGE 4
#define DSMEM (NSTAGE*STAGE) // 98304 -> 2 CTAs/SM

// ---------------------------------------------------------------------------
// Device scratch (h carried as fp16 hi+lo; MMA uses hi only)
// ---------------------------------------------------------------------------
__device__ __half g_ahi[(size_t)MROWS * HDIM];
__device__ __half g_alo[(size_t)MROWS * HDIM];
__device__ __half g_zhi[(size_t)MROWS * HDIM];
__device__ __half g_zlo[(size_t)MROWS * HDIM];
__device__ __half g_w1hi[3 * HDIM * HDIM];
__device__ __half g_w1lo[3 * HDIM * HDIM];
__device__ __half g_w2hi[3 * HDIM * HDIM];
__device__ __half g_w2lo[3 * HDIM * HDIM];
__device__ float g_bvec[MROWS];
__device__ float g_gvec[MROWS];

// ---------------------------------------------------------------------------
// PTX helpers (baseline sm_80+ features only)
// ---------------------------------------------------------------------------
__device__ __forceinline__ uint32_t smem_u32(const void* p) {
    uint32_t a;
    asm("{ .reg .u64 t; cvta.to.shared.u64 t, %1; cvt.u32.u64 %0, t; }" : "=r"(a) : "l"(p));
    return a;
}
__device__ __forceinline__ void cp16(uint32_t dst, const void* src) {
    asm volatile("cp.async.cg.shared.global [%0], [%1], 16;" :: "r"(dst), "l"(src));
}
#define CP_COMMIT() asm volatile("cp.async.commit_group;" ::: "memory")
#define CP_WAIT(n)  asm volatile("cp.async.wait_group %0;" :: "n"(n) : "memory")

__device__ __forceinline__ void ldsm_x4(uint32_t r[4], uint32_t addr) {
    asm volatile("ldmatrix.sync.aligned.m8n8.x4.shared.b16 {%0,%1,%2,%3}, [%4];"
        : "=r"(r[0]), "=r"(r[1]), "=r"(r[2]), "=r"(r[3]) : "r"(addr));
}
__device__ __forceinline__ void mma_f16(float c[4], const uint32_t a[4], const uint32_t b[2]) {
    asm volatile("mma.sync.aligned.m16n8k16.row.col.f32.f16.f16.f32 "
        "{%0,%1,%2,%3}, {%4,%5,%6,%7}, {%8,%9}, {%0,%1,%2,%3};"
        : "+f"(c[0]), "+f"(c[1]), "+f"(c[2]), "+f"(c[3])
        : "r"(a[0]), "r"(a[1]), "r"(a[2]), "r"(a[3]), "r"(b[0]), "r"(b[1]));
}

__device__ __forceinline__ void hsplit(float x, __half& h, __half& l) {
    h = __float2half_rn(x);
    l = __float2half_rn(x - __half2float(h));
}

// Conflict-free XOR swizzle on 16B units within a 64B-pitch row.
__device__ __forceinline__ uint32_t swz(int row, int q) {
    return (uint32_t)(row * 64 + ((q ^ ((row >> 1) & 3)) << 4));
}

// ---------------------------------------------------------------------------
// Weight conversion: fp32 -> fp16 hi/lo
// ---------------------------------------------------------------------------
__global__ __launch_bounds__(256) void wconv_kernel(const float* __restrict__ W1,
                                                    const float* __restrict__ W2)
{
    const int i = blockIdx.x * 256 + threadIdx.x;
    if (i >= 3 * HDIM * HDIM) return;
    __half h, l;
    hsplit(W1[i], h, l); g_w1hi[i] = h; g_w1lo[i] = l;
    hsplit(W2[i], h, l); g_w2hi[i] = h; g_w2lo[i] = l;
}

// ---------------------------------------------------------------------------
// Stage A: ts GEMM (K=28) + concat node_emb ; writes fp16 hi/lo h
// ---------------------------------------------------------------------------
__global__ __launch_bounds__(256) void ts_kernel(
    const float* __restrict__ x_node,
    const float* __restrict__ node_emb,
    const float* __restrict__ W_ts,
    const float* __restrict__ b_ts)
{
    __shared__ float sW[EDIM * LEN];
    __shared__ float sF[64 * LEN];

    const int rowBase = blockIdx.x * 64;
    const int bidx  = rowBase >> 11;
    const int nBase = rowBase & 2047;
    const int tid = threadIdx.x;

    for (int i = tid; i < EDIM * LEN; i += 256) sW[i] = W_ts[i];
    for (int idx = tid; idx < 64 * LEN; idx += 256) {
        int l = idx >> 6;
        int i = idx & 63;
        sF[i * LEN + l] = x_node[((size_t)(bidx * LEN + l)) * NNODE + nBase + i];
    }
    __syncthreads();

    const int e = tid;
    const float bias = b_ts[e];
    const float* wrow = &sW[e * LEN];

    for (int i = 0; i < 64; i++) {
        float acc = bias;
        #pragma unroll
        for (int l = 0; l < LEN; l++)
            acc = fmaf(sF[i * LEN + l], wrow[l], acc);
        const size_t r = (size_t)(rowBase + i) * HDIM;
        const float ne = node_emb[(size_t)(nBase + i) * EDIM + e];
        __half h, l;
        hsplit(acc, h, l); g_ahi[r + e] = h;        g_alo[r + e] = l;
        hsplit(ne, h, l);  g_ahi[r + EDIM + e] = h; g_alo[r + EDIM + e] = l;
    }
}

// ---------------------------------------------------------------------------
// fp16 2-term GEMM on mma.sync: C = A @ (Wh+Wl)^T + bias [+ (Rhi+Rlo)] [relu]
// 4-stage cp.async multistage, conflict-free swizzle.
// ---------------------------------------------------------------------------
template <bool RELU, bool ADDIN>
__global__ void __launch_bounds__(256, 2) gemm_mma(
    const __half* __restrict__ A,
    const __half* __restrict__ Whi, const __half* __restrict__ Wlo,
    const float* __restrict__ bias,
    const __half* __restrict__ Rhi, const __half* __restrict__ Rlo,
    __half* __restrict__ outhi, __half* __restrict__ outlo)
{
    extern __shared__ char dsm[];
    __shared__ float sbias[BN];

    const int tid = threadIdx.x;
    const int wid = tid >> 5;
    const int lane = tid & 31;
    const int warp_m = wid & 1;
    const int warp_n = wid >> 1;
    const int rowBase = blockIdx.y * BM;
    const int colBase = blockIdx.x * BN;

    if (tid < BN) sbias[tid] = bias[colBase + tid];

    const uint32_t sb = smem_u32(dsm);

    float c[4][4][4];
    #pragma unroll
    for (int i = 0; i < 4; i++)
        #pragma unroll
        for (int j = 0; j < 4; j++)
            #pragma unroll
            for (int k = 0; k < 4; k++) c[i][j][k] = 0.f;

    // ---- chunk loader: 512 16B-chunks per array, 3 arrays, 6 cp16/thread ----
    auto load_chunk = [&](int cidx, int s) {
        const uint32_t base = sb + (uint32_t)s * STAGE;
        const int kk = cidx * BK;
        #pragma unroll
        for (int j = 0; j < 2; j++) {
            const int ch = tid * 2 + j;
            const int row = ch >> 2;
            const int q = ch & 3;
            const uint32_t doff = swz(row, q);
            const int eoff = kk + q * 8;       // 8 fp16 per 16B
            cp16(base + OA  + doff, A   + (size_t)(rowBase + row) * HDIM + eoff);
            cp16(base + OWH + doff, Whi + (size_t)(colBase + row) * HDIM + eoff);
            cp16(base + OWL + doff, Wlo + (size_t)(colBase + row) * HDIM + eoff);
        }
        CP_COMMIT();
    };

    // ---- fragment addressing ----
    const int ra  = warp_m * 64 + (lane & 15);
    const int qa  = lane >> 4;
    const int rb  = warp_n * 32 + ((lane >> 4) & 1) * 8 + (lane & 7);
    const int qb  = (lane >> 3) & 1;

    auto compute = [&](int s) {
        const uint32_t base = sb + (uint32_t)s * STAGE;
        #pragma unroll
        for (int ks = 0; ks < 2; ks++) {
            // B fragments for all 4 nf (hi and lo): 4 x ldsm_x4
            uint32_t wh[2][4], wl[2][4];
            #pragma unroll
            for (int p = 0; p < 2; p++) {
                const uint32_t boff = swz(rb + p * 16, qb + 2 * ks);
                ldsm_x4(wh[p], base + OWH + boff);
                ldsm_x4(wl[p], base + OWL + boff);
            }
            // A fragments streamed per-mf with 1-deep double buffer
            const uint32_t aoff = swz(ra, qa + 2 * ks);
            uint32_t a[2][4];
            ldsm_x4(a[0], base + OA + aoff);
            #pragma unroll
            for (int mf = 0; mf < 4; mf++) {
                const int cur = mf & 1, nxt = cur ^ 1;
                if (mf < 3)
                    ldsm_x4(a[nxt], base + OA + aoff + (uint32_t)((mf + 1) * 1024));
                #pragma unroll
                for (int nf = 0; nf < 4; nf++)
                    mma_f16(c[mf][nf], a[cur], &wh[nf >> 1][(nf & 1) * 2]);
                #pragma unroll
                for (int nf = 0; nf < 4; nf++)
                    mma_f16(c[mf][nf], a[cur], &wl[nf >> 1][(nf & 1) * 2]);
            }
        }
    };

    // ---- multistage mainloop: 1 sync per chunk, depth-3 prefetch ----
    load_chunk(0, 0);
    load_chunk(1, 1);
    load_chunk(2, 2);
    CP_WAIT(2);            // chunk 0 landed
    __syncthreads();

    for (int m = 0; m < NCHUNK; m++) {
        if (m + 3 < NCHUNK) load_chunk(m + 3, (m + 3) & 3);
        compute(m & 3);
        if (m + 3 < NCHUNK)      { CP_WAIT(2); }   // chunk m+1 landed
        else if (m + 2 < NCHUNK) { CP_WAIT(1); }
        else if (m + 1 < NCHUNK) { CP_WAIT(0); }
        __syncthreads();
    }

    // ---- epilogue: fragments -> smem staging (coalesce), then gmem ----
    float* stg = (float*)dsm;   // 128 x 132 fp32 = 67584 B
    #pragma unroll
    for (int mf = 0; mf < 4; mf++) {
        #pragma unroll
        for (int nf = 0; nf < 4; nf++) {
            const int r0 = warp_m * 64 + mf * 16 + (lane >> 2);
            const int cc = warp_n * 32 + nf * 8 + 2 * (lane & 3);
            *(float2*)&stg[(size_t)r0 * 132 + cc]       = make_float2(c[mf][nf][0], c[mf][nf][1]);
            *(float2*)&stg[(size_t)(r0 + 8) * 132 + cc] = make_float2(c[mf][nf][2], c[mf][nf][3]);
        }
    }
    __syncthreads();

    for (int rr = 0; rr < 16; rr++) {
        const int r = wid * 16 + rr;
        const size_t grow = (size_t)(rowBase + r) * HDIM;
        #pragma unroll
        for (int p = 0; p < 4; p++) {
            const int col = p * 32 + lane;
            float v = stg[(size_t)r * 132 + col] + sbias[col];
            const size_t gi = grow + colBase + col;
            if (ADDIN)
                v += __half2float(Rhi[gi]) + __half2float(Rlo[gi]);
            if (RELU) v = fmaxf(v, 0.f);
            __half h, l;
            hsplit(v, h, l);
            outhi[gi] = h; outlo[gi] = l;
        }
    }
}

// ---------------------------------------------------------------------------
// Stage C: b = sigmoid(h@Wb^T+bb), g = sigmoid(h@Wg^T+bg); h = hi+lo
// ---------------------------------------------------------------------------
__global__ __launch_bounds__(256) void bg_kernel(
    const float* __restrict__ Wb, const float* __restrict__ bbias,
    const float* __restrict__ Wg, const float* __restrict__ gbias)
{
    __shared__ float sWb[HDIM];
    __shared__ float sWg[HDIM];
    const int tid = threadIdx.x;
    for (int i = tid; i < HDIM; i += 256) { sWb[i] = Wb[i]; sWg[i] = Wg[i]; }
    __syncthreads();

    const int warp = tid >> 5;
    const int lane = tid & 31;
    const size_t row = (size_t)blockIdx.x * 8 + warp;
    const __half* hh = g_ahi + row * HDIM;
    const __half* hl = g_alo + row * HDIM;

    float accb = 0.f, accg = 0.f;
    #pragma unroll
    for (int i = 0; i < HDIM / 32; i++) {
        const int idx = lane + i * 32;
        const float hv = __half2float(hh[idx]) + __half2float(hl[idx]);
        accb = fmaf(hv, sWb[idx], accb);
        accg = fmaf(hv, sWg[idx], accg);
    }
    #pragma unroll
    for (int o = 16; o; o >>= 1) {
        accb += __shfl_xor_sync(0xFFFFFFFFu, accb, o);
        accg += __shfl_xor_sync(0xFFFFFFFFu, accg, o);
    }
    if (lane == 0) {
        g_bvec[row] = 1.f / (1.f + expf(-(accb + bbias[0])));
        g_gvec[row] = 1.f / (1.f + expf(-(accg + gbias[0])));
    }
}

// ---------------------------------------------------------------------------
// Stage D: SIR reconstruction + 28-step scan
// ---------------------------------------------------------------------------
__global__ __launch_bounds__(256) void sim_kernel(
    const float* __restrict__ x_state, float* __restrict__ out)
{
    const size_t r = (size_t)blockIdx.x * blockDim.x + threadIdx.x;
    const int b = (int)(r >> 11);
    const int n = (int)(r & 2047);

    const float beta = g_bvec[r];
    const float g    = g_gvec[r];
    const float decay = expf(-g);
    const float inv_g = 1.f / g;

    const float* xs = x_state + ((size_t)b * LEN * NNODE + n) * 3;
    const int TSTRIDE = NNODE * 3;

    float Iprev = xs[0 * TSTRIDE + 1];
    float acc = 0.f;
    #pragma unroll
    for (int t = 1; t <= LEN - 1; t++) {
        const float Icur = xs[t * TSTRIDE + 1];
        const float iin = fmaxf((Icur - Iprev) * inv_g + Iprev, 0.f);
        acc = fmaf(acc, decay, iin);
        Iprev = Icur;
    }

    const float Npop  = xs[(LEN - 1) * TSTRIDE + 2];
    const float R_Tm1 = Npop - xs[(LEN - 2) * TSTRIDE + 0];
    const float I_Tm1 = decay * acc;
    const float S_Tm1 = Npop - I_Tm1 - R_Tm1;
    const float Iin0  = beta * S_Tm1 * I_Tm1 / Npop;

    float S = S_Tm1 - Iin0;
    float I = decay * (I_Tm1 + Iin0);

    float* op = out + (size_t)b * LEN * NNODE + n;
    #pragma unroll
    for (int t = 0; t < LEN; t++) {
        const float Iin = beta * S * I / Npop;
        S -= Iin;
        const float Rin = g * I;
        I = decay * (I + Iin);
        op[(size_t)t * NNODE] = Rin;
    }
}

// ---------------------------------------------------------------------------
extern "C" void kernel_launch(void* const* d_in, const int* in_sizes, int n_in,
                              void* d_out, int out_size)
{
    (void)in_sizes; (void)n_in; (void)out_size;
    const float* x_node   = (const float*)d_in[0];
    const float* x_state  = (const float*)d_in[1];
    const float* node_emb = (const float*)d_in[2];
    const float* W_ts     = (const float*)d_in[3];
    const float* b_ts     = (const float*)d_in[4];
    const float* enc_W1   = (const float*)d_in[5];
    const float* enc_b1   = (const float*)d_in[6];
    const float* enc_W2   = (const float*)d_in[7];
    const float* enc_b2   = (const float*)d_in[8];
    const float* Wb       = (const float*)d_in[9];
    const float* bb       = (const float*)d_in[10];
    const float* Wg       = (const float*)d_in[11];
    const float* bg       = (const float*)d_in[12];
    float* out = (float*)d_out;

    __half *ahi, *alo, *zhi, *zlo, *w1hi, *w1lo, *w2hi, *w2lo;
    cudaGetSymbolAddress((void**)&ahi, g_ahi);
    cudaGetSymbolAddress((void**)&alo, g_alo);
    cudaGetSymbolAddress((void**)&zhi, g_zhi);
    cudaGetSymbolAddress((void**)&zlo, g_zlo);
    cudaGetSymbolAddress((void**)&w1hi, g_w1hi);
    cudaGetSymbolAddress((void**)&w1lo, g_w1lo);
    cudaGetSymbolAddress((void**)&w2hi, g_w2hi);
    cudaGetSymbolAddress((void**)&w2lo, g_w2lo);

    cudaFuncSetAttribute(gemm_mma<true,  false>, cudaFuncAttributeMaxDynamicSharedMemorySize, DSMEM);
    cudaFuncSetAttribute(gemm_mma<false, true >, cudaFuncAttributeMaxDynamicSharedMemorySize, DSMEM);

    // weights -> fp16 hi/lo
    wconv_kernel<<<(3 * HDIM * HDIM + 255) / 256, 256>>>(enc_W1, enc_W2);

    // Stage A
    ts_kernel<<<MROWS / 64, 256>>>(x_node, node_emb, W_ts, b_ts);

    // Stage B: 3 residual layers on tensor cores (fp16 2-term mma.sync)
    const dim3 grid(HDIM / BN, MROWS / BM);   // (4, 512)
    for (int l = 0; l < 3; l++) {
        const __half* W1h = w1hi + (size_t)l * HDIM * HDIM;
        const __half* W1l = w1lo + (size_t)l * HDIM * HDIM;
        const __half* W2h = w2hi + (size_t)l * HDIM * HDIM;
        const __half* W2l = w2lo + (size_t)l * HDIM * HDIM;
        const float* B1 = enc_b1 + (size_t)l * HDIM;
        const float* B2 = enc_b2 + (size_t)l * HDIM;

        // z = relu(h @ W1^T + b1)
        gemm_mma<true, false><<<grid, 256, DSMEM>>>(
            ahi, W1h, W1l, B1, nullptr, nullptr, zhi, zlo);
        // h = h + z @ W2^T + b2   (in-place hi/lo update)
        gemm_mma<false, true><<<grid, 256, DSMEM>>>(
            zhi, W2h, W2l, B2, ahi, alo, ahi, alo);
    }

    // Stage C + D
    bg_kernel<<<MROWS / 8, 256>>>(Wb, bb, Wg, bg);
    sim_kernel<<<MROWS / 256, 256>>>(x_state, out);
}